// round 10
// baseline (speedup 1.0000x reference)
#include <cuda_runtime.h>
#include <math.h>

#define N_NODES 50000
#define N_EDGES 800000
#define NHEAD 8
#define HIDD 32
#define FDIM 256
#define NEG_SLOPE 0.2f
#define NSCAN_BLOCKS 196   /* ceil(50000/256) */

// ---------------- scratch ----------------
__device__ float g_feat[N_NODES * FDIM];
__device__ float g_h1  [N_NODES * FDIM];
__device__ float g_h2  [N_NODES * FDIM];
__device__ float g_el  [N_NODES * NHEAD];
__device__ float g_er  [N_NODES * NHEAD];
__device__ float g_csum[FDIM];
__device__ int   g_cnt [N_NODES];
__device__ int   g_rows[N_NODES + 1];
__device__ int   g_cur [N_NODES];
__device__ int   g_csrc[N_EDGES];
__device__ int   g_bsum[NSCAN_BLOCKS];
__device__ int   g_boff[NSCAN_BLOCKS];

// ================= CSR build =================
__global__ void zero_cnt(int* cnt) {
    int i = blockIdx.x * blockDim.x + threadIdx.x;
    if (i < N_NODES) cnt[i] = 0;
}
__global__ void hist_k(const int* __restrict__ dst, int* __restrict__ cnt) {
    int e = blockIdx.x * blockDim.x + threadIdx.x;
    if (e < N_EDGES) atomicAdd(&cnt[dst[e]], 1);
}
// two-level scan: per-block exclusive scan + block totals
__global__ __launch_bounds__(256) void scan1_k(const int* __restrict__ cnt,
                                               int* __restrict__ rows,
                                               int* __restrict__ bsum) {
    __shared__ int ws[8];
    int t = threadIdx.x, lane = t & 31, w = t >> 5;
    int i = blockIdx.x * 256 + t;
    int v = (i < N_NODES) ? cnt[i] : 0;
    int x = v;
#pragma unroll
    for (int o = 1; o < 32; o <<= 1) {
        int y = __shfl_up_sync(0xffffffffu, x, o);
        if (lane >= o) x += y;
    }
    if (lane == 31) ws[w] = x;
    __syncthreads();
    if (w == 0 && lane < 8) {
        int y = ws[lane];
#pragma unroll
        for (int o = 1; o < 8; o <<= 1) {
            int z = __shfl_up_sync(0x000000ffu, y, o);
            if (lane >= o) y += z;
        }
        ws[lane] = y;
    }
    __syncthreads();
    int excl = x - v + (w ? ws[w - 1] : 0);
    if (i < N_NODES) rows[i] = excl;
    if (t == 255) bsum[blockIdx.x] = excl + v;
}
__global__ __launch_bounds__(256) void scan2_k(const int* __restrict__ bsum,
                                               int* __restrict__ boff) {
    __shared__ int ws[8];
    int t = threadIdx.x, lane = t & 31, w = t >> 5;
    int v = (t < NSCAN_BLOCKS) ? bsum[t] : 0;
    int x = v;
#pragma unroll
    for (int o = 1; o < 32; o <<= 1) {
        int y = __shfl_up_sync(0xffffffffu, x, o);
        if (lane >= o) x += y;
    }
    if (lane == 31) ws[w] = x;
    __syncthreads();
    if (w == 0 && lane < 8) {
        int y = ws[lane];
#pragma unroll
        for (int o = 1; o < 8; o <<= 1) {
            int z = __shfl_up_sync(0x000000ffu, y, o);
            if (lane >= o) y += z;
        }
        ws[lane] = y;
    }
    __syncthreads();
    if (t < NSCAN_BLOCKS) boff[t] = x - v + (w ? ws[w - 1] : 0);
}
__global__ __launch_bounds__(256) void scan3_k(int* __restrict__ rows,
                                               const int* __restrict__ boff,
                                               int* __restrict__ cur) {
    int i = blockIdx.x * 256 + threadIdx.x;
    if (i < N_NODES) {
        int r = rows[i] + boff[blockIdx.x];
        rows[i] = r;
        cur[i]  = r;
    }
    if (i == 0) rows[N_NODES] = N_EDGES;
}
__global__ void scatter_k(const int* __restrict__ src, const int* __restrict__ dst,
                          int* __restrict__ cur, int* __restrict__ csrc) {
    int e = blockIdx.x * blockDim.x + threadIdx.x;
    if (e < N_EDGES) {
        int pos = atomicAdd(&cur[dst[e]], 1);
        csrc[pos] = src[e];
    }
}

// ================= TF32 tensor-core GEMM + fused el/er epilogue =================
// C[M,256] = A[M,K] @ B[K,256]; el[m,h] = sum_d C[m,h*32+d]*al[h,d] (same for er).
// block tile 128x128, 8 warps in 2x4; warp tile 64x32 = 4x4 mma(16x8); k-block 16.
// warp wn's 32 columns == head (blockIdx.x*4 + wn) exactly.
__device__ __forceinline__ unsigned f2tf(float f) {
    unsigned u;
    asm("cvt.rna.tf32.f32 %0, %1;" : "=r"(u) : "f"(f));
    return u;
}
__device__ __forceinline__ void mma_tf32(float c[4], const unsigned a[4], const unsigned b[2]) {
    asm volatile(
        "mma.sync.aligned.m16n8k8.row.col.f32.tf32.tf32.f32 "
        "{%0,%1,%2,%3}, {%4,%5,%6,%7}, {%8,%9}, {%0,%1,%2,%3};\n"
        : "+f"(c[0]), "+f"(c[1]), "+f"(c[2]), "+f"(c[3])
        : "r"(a[0]), "r"(a[1]), "r"(a[2]), "r"(a[3]), "r"(b[0]), "r"(b[1]));
}

#define GM 128
#define GN 128
#define GKB 16

__global__ __launch_bounds__(256, 2) void sgemm_tf32(const float* __restrict__ A,
                                                     const float* __restrict__ B,
                                                     float* __restrict__ C,
                                                     const float* __restrict__ al,
                                                     const float* __restrict__ ar,
                                                     float* __restrict__ el,
                                                     float* __restrict__ er,
                                                     int M, int K) {
    __shared__ unsigned As[2][GM][20];
    __shared__ unsigned Bs[2][GKB][136];
    int tid  = threadIdx.x;
    int warp = tid >> 5, lane = tid & 31;
    int wm = warp >> 2, wn = warp & 3;
    int rowBase = blockIdx.y * GM;
    int colBase = blockIdx.x * GN;
    int nk = K / GKB;

    int qr = lane >> 2, qc = lane & 3;

    int a_row0 = tid >> 2,        a_c0 = (tid & 3) * 4;
    int a_row1 = (tid >> 2) + 64, a_c1 = a_c0;
    int b_row0 = tid >> 5,        b_c0 = (tid & 31) * 4;
    int b_row1 = (tid >> 5) + 8;

    const float4 fz = make_float4(0.f, 0.f, 0.f, 0.f);
    float4 pa0, pa1, pb0, pb1;

    {
        int g0 = rowBase + a_row0, g1 = rowBase + a_row1;
        pa0 = (g0 < M) ? *(const float4*)(A + (long)g0 * K + a_c0) : fz;
        pa1 = (g1 < M) ? *(const float4*)(A + (long)g1 * K + a_c1) : fz;
        pb0 = *(const float4*)(B + (long)b_row0 * FDIM + colBase + b_c0);
        pb1 = *(const float4*)(B + (long)b_row1 * FDIM + colBase + b_c0);
    }
    {
        unsigned* pA0 = &As[0][a_row0][a_c0];
        pA0[0] = f2tf(pa0.x); pA0[1] = f2tf(pa0.y); pA0[2] = f2tf(pa0.z); pA0[3] = f2tf(pa0.w);
        unsigned* pA1 = &As[0][a_row1][a_c1];
        pA1[0] = f2tf(pa1.x); pA1[1] = f2tf(pa1.y); pA1[2] = f2tf(pa1.z); pA1[3] = f2tf(pa1.w);
        unsigned* pB0 = &Bs[0][b_row0][b_c0];
        pB0[0] = f2tf(pb0.x); pB0[1] = f2tf(pb0.y); pB0[2] = f2tf(pb0.z); pB0[3] = f2tf(pb0.w);
        unsigned* pB1 = &Bs[0][b_row1][b_c0];
        pB1[0] = f2tf(pb1.x); pB1[1] = f2tf(pb1.y); pB1[2] = f2tf(pb1.z); pB1[3] = f2tf(pb1.w);
    }
    __syncthreads();

    float cacc[4][4][4] = {};

    for (int kb = 0; kb < nk; kb++) {
        int nb = kb + 1;
        if (nb < nk) {
            int koff = nb * GKB;
            int g0 = rowBase + a_row0, g1 = rowBase + a_row1;
            pa0 = (g0 < M) ? *(const float4*)(A + (long)g0 * K + koff + a_c0) : fz;
            pa1 = (g1 < M) ? *(const float4*)(A + (long)g1 * K + koff + a_c1) : fz;
            pb0 = *(const float4*)(B + (long)(koff + b_row0) * FDIM + colBase + b_c0);
            pb1 = *(const float4*)(B + (long)(koff + b_row1) * FDIM + colBase + b_c0);
        }
        int cb = kb & 1;
#pragma unroll
        for (int ks = 0; ks < GKB; ks += 8) {
            unsigned af[4][4], bf[4][2];
#pragma unroll
            for (int mi = 0; mi < 4; mi++) {
                int r = wm * 64 + mi * 16 + qr;
                int c = ks + qc;
                af[mi][0] = As[cb][r][c];
                af[mi][1] = As[cb][r + 8][c];
                af[mi][2] = As[cb][r][c + 4];
                af[mi][3] = As[cb][r + 8][c + 4];
            }
#pragma unroll
            for (int ni = 0; ni < 4; ni++) {
                int n = wn * 32 + ni * 8 + qr;
                int k = ks + qc;
                bf[ni][0] = Bs[cb][k][n];
                bf[ni][1] = Bs[cb][k + 4][n];
            }
#pragma unroll
            for (int mi = 0; mi < 4; mi++)
#pragma unroll
                for (int ni = 0; ni < 4; ni++)
                    mma_tf32(cacc[mi][ni], af[mi], bf[ni]);
        }
        if (nb < nk) {
            int wb = nb & 1;
            unsigned* pA0 = &As[wb][a_row0][a_c0];
            pA0[0] = f2tf(pa0.x); pA0[1] = f2tf(pa0.y); pA0[2] = f2tf(pa0.z); pA0[3] = f2tf(pa0.w);
            unsigned* pA1 = &As[wb][a_row1][a_c1];
            pA1[0] = f2tf(pa1.x); pA1[1] = f2tf(pa1.y); pA1[2] = f2tf(pa1.z); pA1[3] = f2tf(pa1.w);
            unsigned* pB0 = &Bs[wb][b_row0][b_c0];
            pB0[0] = f2tf(pb0.x); pB0[1] = f2tf(pb0.y); pB0[2] = f2tf(pb0.z); pB0[3] = f2tf(pb0.w);
            unsigned* pB1 = &Bs[wb][b_row1][b_c0];
            pB1[0] = f2tf(pb1.x); pB1[1] = f2tf(pb1.y); pB1[2] = f2tf(pb1.z); pB1[3] = f2tf(pb1.w);
        }
        __syncthreads();
    }

    // store C
#pragma unroll
    for (int mi = 0; mi < 4; mi++) {
        int r0 = rowBase + wm * 64 + mi * 16 + qr;
        int r1 = r0 + 8;
#pragma unroll
        for (int ni = 0; ni < 4; ni++) {
            int c = colBase + wn * 32 + ni * 8 + 2 * qc;
            if (r0 < M) {
                float2 v = make_float2(cacc[mi][ni][0], cacc[mi][ni][1]);
                *(float2*)(C + (long)r0 * FDIM + c) = v;
            }
            if (r1 < M) {
                float2 v = make_float2(cacc[mi][ni][2], cacc[mi][ni][3]);
                *(float2*)(C + (long)r1 * FDIM + c) = v;
            }
        }
    }

    // fused el/er epilogue: warp wn's 32 cols == head h, complete dot per row
    {
        int h = blockIdx.x * 4 + wn;
        float alv[8], arv[8];
#pragma unroll
        for (int ni = 0; ni < 4; ni++) {
            int d = ni * 8 + 2 * qc;
            alv[ni * 2]     = al[h * HIDD + d];
            alv[ni * 2 + 1] = al[h * HIDD + d + 1];
            arv[ni * 2]     = ar[h * HIDD + d];
            arv[ni * 2 + 1] = ar[h * HIDD + d + 1];
        }
#pragma unroll
        for (int mi = 0; mi < 4; mi++) {
            float sl0 = 0.f, sr0 = 0.f, sl1 = 0.f, sr1 = 0.f;
#pragma unroll
            for (int ni = 0; ni < 4; ni++) {
                sl0 += cacc[mi][ni][0] * alv[ni * 2] + cacc[mi][ni][1] * alv[ni * 2 + 1];
                sr0 += cacc[mi][ni][0] * arv[ni * 2] + cacc[mi][ni][1] * arv[ni * 2 + 1];
                sl1 += cacc[mi][ni][2] * alv[ni * 2] + cacc[mi][ni][3] * alv[ni * 2 + 1];
                sr1 += cacc[mi][ni][2] * arv[ni * 2] + cacc[mi][ni][3] * arv[ni * 2 + 1];
            }
#pragma unroll
            for (int o = 1; o < 4; o <<= 1) {
                sl0 += __shfl_xor_sync(0xffffffffu, sl0, o);
                sr0 += __shfl_xor_sync(0xffffffffu, sr0, o);
                sl1 += __shfl_xor_sync(0xffffffffu, sl1, o);
                sr1 += __shfl_xor_sync(0xffffffffu, sr1, o);
            }
            if (qc == 0) {
                int r0 = rowBase + wm * 64 + mi * 16 + qr;
                int r1 = r0 + 8;
                if (r0 < M) { el[r0 * NHEAD + h] = sl0; er[r0 * NHEAD + h] = sr0; }
                if (r1 < M) { el[r1 * NHEAD + h] = sl1; er[r1 * NHEAD + h] = sr1; }
            }
        }
    }
}

// ================= fused single-pass GAT aggregation =================
// one warp per dst node; lane owns cols [lane*8, lane*8+8); head = lane>>2.
// csrc prefetched coalesced (one 128B load / 32 edges) + shfl broadcast;
// edge loop unrolled x2 for memory-level parallelism.
__global__ __launch_bounds__(256) void gat_aggr(const int* __restrict__ rows,
                                                const int* __restrict__ csrc,
                                                const float* __restrict__ el,
                                                const float* __restrict__ er,
                                                const float* __restrict__ feat,
                                                const float* __restrict__ hres,
                                                const float* __restrict__ bias,
                                                float* __restrict__ hout) {
    int tid  = threadIdx.x;
    int node = (blockIdx.x * blockDim.x + tid) >> 5;   // grid sized exactly -> always valid
    int lane = tid & 31;
    int myh  = lane >> 2;

    int e0 = rows[node], e1 = rows[node + 1];
    float er_my = er[node * NHEAD + myh];

    float acc[8] = {};
    float den = 0.f;
    const float4* f4 = (const float4*)feat;
    for (int base = e0; base < e1; base += 32) {
        int idx = base + lane;
        int sl = csrc[(idx < e1) ? idx : (e1 - 1)];    // coalesced
        int n = min(32, e1 - base);
        int j = 0;
        for (; j + 2 <= n; j += 2) {
            int s0 = __shfl_sync(0xffffffffu, sl, j);
            int s1 = __shfl_sync(0xffffffffu, sl, j + 1);
            float v0 = __ldg(&el[s0 * NHEAD + myh]) + er_my;
            float v1 = __ldg(&el[s1 * NHEAD + myh]) + er_my;
            float4 x0 = f4[(long)s0 * 64 + lane * 2];
            float4 x1 = f4[(long)s0 * 64 + lane * 2 + 1];
            float4 y0 = f4[(long)s1 * 64 + lane * 2];
            float4 y1 = f4[(long)s1 * 64 + lane * 2 + 1];
            v0 = (v0 > 0.f) ? v0 : NEG_SLOPE * v0;
            v1 = (v1 > 0.f) ? v1 : NEG_SLOPE * v1;
            float a = __expf(v0);
            float b = __expf(v1);
            den += a + b;
            acc[0] += a * x0.x + b * y0.x; acc[1] += a * x0.y + b * y0.y;
            acc[2] += a * x0.z + b * y0.z; acc[3] += a * x0.w + b * y0.w;
            acc[4] += a * x1.x + b * y1.x; acc[5] += a * x1.y + b * y1.y;
            acc[6] += a * x1.z + b * y1.z; acc[7] += a * x1.w + b * y1.w;
        }
        if (j < n) {
            int s0 = __shfl_sync(0xffffffffu, sl, j);
            float v0 = __ldg(&el[s0 * NHEAD + myh]) + er_my;
            float4 x0 = f4[(long)s0 * 64 + lane * 2];
            float4 x1 = f4[(long)s0 * 64 + lane * 2 + 1];
            v0 = (v0 > 0.f) ? v0 : NEG_SLOPE * v0;
            float a = __expf(v0);
            den += a;
            acc[0] += a * x0.x; acc[1] += a * x0.y; acc[2] += a * x0.z; acc[3] += a * x0.w;
            acc[4] += a * x1.x; acc[5] += a * x1.y; acc[6] += a * x1.z; acc[7] += a * x1.w;
        }
    }
    float inv = (den == 0.f) ? 1.f : 1.f / den;

    float4 b0 = ((const float4*)bias)[lane * 2];
    float4 b1 = ((const float4*)bias)[lane * 2 + 1];
    float bv[8] = {b0.x, b0.y, b0.z, b0.w, b1.x, b1.y, b1.z, b1.w};
    float rv[8] = {};
    if (hres) {
        float4 r0 = ((const float4*)(hres + (long)node * FDIM))[lane * 2];
        float4 r1 = ((const float4*)(hres + (long)node * FDIM))[lane * 2 + 1];
        rv[0] = r0.x; rv[1] = r0.y; rv[2] = r0.z; rv[3] = r0.w;
        rv[4] = r1.x; rv[5] = r1.y; rv[6] = r1.z; rv[7] = r1.w;
    }
    float o[8];
#pragma unroll
    for (int j = 0; j < 8; j++) {
        float val = acc[j] * inv + rv[j] + bv[j];
        o[j] = (val > 0.f) ? val : expm1f(val);
    }
    float* op = hout + (long)node * FDIM + lane * 8;
    *(float4*)op       = make_float4(o[0], o[1], o[2], o[3]);
    *(float4*)(op + 4) = make_float4(o[4], o[5], o[6], o[7]);
}

// ================= mean -> linear (commuted) =================
__global__ void zero_csum(float* c) { c[threadIdx.x] = 0.f; }

__global__ __launch_bounds__(256) void colsum_k(const float* __restrict__ h,
                                                float* __restrict__ csum) {
    int col = threadIdx.x;
    int r0 = blockIdx.x * 256;
    int r1 = min(r0 + 256, N_NODES);
    float s = 0.f;
    for (int r = r0; r < r1; r++) s += h[(long)r * FDIM + col];
    atomicAdd(&csum[col], s);
}

__global__ void final_k(const float* __restrict__ csum,
                        const float* __restrict__ Wl,
                        const float* __restrict__ bl,
                        float* __restrict__ out) {
    int j = threadIdx.x;
    float s = 0.f;
    for (int c = 0; c < FDIM; c++) s += csum[c] * Wl[c * 128 + j];
    out[j] = s * (1.f / (float)N_NODES) + bl[j];
}

// ================= host =================
extern "C" void kernel_launch(void* const* d_in, const int* in_sizes, int n_in,
                              void* d_out, int out_size) {
    const float* x   = (const float*)d_in[0];
    const int*   src = (const int*)  d_in[1];
    const int*   dst = (const int*)  d_in[2];
    const float* W1  = (const float*)d_in[3];
    const float* al1 = (const float*)d_in[4];
    const float* ar1 = (const float*)d_in[5];
    const float* b1  = (const float*)d_in[6];
    const float* W2  = (const float*)d_in[7];
    const float* al2 = (const float*)d_in[8];
    const float* ar2 = (const float*)d_in[9];
    const float* b2  = (const float*)d_in[10];
    const float* Wl  = (const float*)d_in[11];
    const float* bl  = (const float*)d_in[12];
    float* out = (float*)d_out;

    float *feat, *h1, *h2, *el, *er, *csum;
    int *cnt, *rows, *cur, *csrc, *bsum, *boff;
    cudaGetSymbolAddress((void**)&feat, g_feat);
    cudaGetSymbolAddress((void**)&h1,   g_h1);
    cudaGetSymbolAddress((void**)&h2,   g_h2);
    cudaGetSymbolAddress((void**)&el,   g_el);
    cudaGetSymbolAddress((void**)&er,   g_er);
    cudaGetSymbolAddress((void**)&csum, g_csum);
    cudaGetSymbolAddress((void**)&cnt,  g_cnt);
    cudaGetSymbolAddress((void**)&rows, g_rows);
    cudaGetSymbolAddress((void**)&cur,  g_cur);
    cudaGetSymbolAddress((void**)&csrc, g_csrc);
    cudaGetSymbolAddress((void**)&bsum, g_bsum);
    cudaGetSymbolAddress((void**)&boff, g_boff);

    int nodeBlocks     = (N_NODES + 255) / 256;     // 196
    int edgeBlocks     = (N_EDGES + 255) / 256;
    int nodeWarpBlocks = (N_NODES * 32) / 256;      // 6250 exact
    dim3 gemm_grid(FDIM / GN, (N_NODES + GM - 1) / GM);

    // CSR build + layer-1 projection (sgemm is 4th launch -> profiled)
    zero_cnt<<<nodeBlocks, 256>>>(cnt);
    hist_k<<<edgeBlocks, 256>>>(dst, cnt);
    scan1_k<<<nodeBlocks, 256>>>(cnt, rows, bsum);
    sgemm_tf32<<<gemm_grid, 256>>>(x, W1, feat, al1, ar1, el, er, N_NODES, 128);
    scan2_k<<<1, 256>>>(bsum, boff);
    scan3_k<<<nodeBlocks, 256>>>(rows, boff, cur);
    scatter_k<<<edgeBlocks, 256>>>(src, dst, cur, csrc);

    // layer 1 aggregation (no residual)
    gat_aggr<<<nodeWarpBlocks, 256>>>(rows, csrc, el, er, feat, nullptr, b1, h1);

    // layer 2 (identity residual)
    sgemm_tf32<<<gemm_grid, 256>>>(h1, W2, feat, al2, ar2, el, er, N_NODES, 256);
    gat_aggr<<<nodeWarpBlocks, 256>>>(rows, csrc, el, er, feat, h1, b2, h2);

    // out = colmean(h2) @ Wl + bl
    zero_csum<<<1, FDIM>>>(csum);
    colsum_k<<<nodeBlocks, 256>>>(h2, csum);
    final_k<<<1, 128>>>(csum, Wl, bl, out);
}

// round 11
// speedup vs baseline: 1.2763x; 1.2763x over previous
#include <cuda_runtime.h>
#include <math.h>

#define N_NODES 50000
#define N_EDGES 800000
#define NHEAD 8
#define HIDD 32
#define FDIM 256
#define NEG_SLOPE 0.2f
#define NSCAN_BLOCKS 196   /* ceil(50000/256) */

// ---------------- scratch ----------------
__device__ float g_feat[N_NODES * FDIM];
__device__ float g_h1  [N_NODES * FDIM];
__device__ float g_h2  [N_NODES * FDIM];
__device__ float g_el  [N_NODES * NHEAD];
__device__ float g_er  [N_NODES * NHEAD];
__device__ float g_csum[FDIM];
__device__ int   g_cnt [N_NODES];
__device__ int   g_rows[N_NODES + 1];
__device__ int   g_cur [N_NODES];
__device__ int   g_csrc[N_EDGES];
__device__ int   g_bsum[NSCAN_BLOCKS];
__device__ int   g_boff[NSCAN_BLOCKS];

// ================= CSR build =================
__global__ void zero_cnt(int* cnt) {
    int i = blockIdx.x * blockDim.x + threadIdx.x;
    if (i < N_NODES) cnt[i] = 0;
}
__global__ void hist_k(const int* __restrict__ dst, int* __restrict__ cnt) {
    int e = blockIdx.x * blockDim.x + threadIdx.x;
    if (e < N_EDGES) atomicAdd(&cnt[dst[e]], 1);
}
// two-level scan
__global__ __launch_bounds__(256) void scan1_k(const int* __restrict__ cnt,
                                               int* __restrict__ rows,
                                               int* __restrict__ bsum) {
    __shared__ int ws[8];
    int t = threadIdx.x, lane = t & 31, w = t >> 5;
    int i = blockIdx.x * 256 + t;
    int v = (i < N_NODES) ? cnt[i] : 0;
    int x = v;
#pragma unroll
    for (int o = 1; o < 32; o <<= 1) {
        int y = __shfl_up_sync(0xffffffffu, x, o);
        if (lane >= o) x += y;
    }
    if (lane == 31) ws[w] = x;
    __syncthreads();
    if (w == 0 && lane < 8) {
        int y = ws[lane];
#pragma unroll
        for (int o = 1; o < 8; o <<= 1) {
            int z = __shfl_up_sync(0x000000ffu, y, o);
            if (lane >= o) y += z;
        }
        ws[lane] = y;
    }
    __syncthreads();
    int excl = x - v + (w ? ws[w - 1] : 0);
    if (i < N_NODES) rows[i] = excl;
    if (t == 255) bsum[blockIdx.x] = excl + v;
}
__global__ __launch_bounds__(256) void scan2_k(const int* __restrict__ bsum,
                                               int* __restrict__ boff) {
    __shared__ int ws[8];
    int t = threadIdx.x, lane = t & 31, w = t >> 5;
    int v = (t < NSCAN_BLOCKS) ? bsum[t] : 0;
    int x = v;
#pragma unroll
    for (int o = 1; o < 32; o <<= 1) {
        int y = __shfl_up_sync(0xffffffffu, x, o);
        if (lane >= o) x += y;
    }
    if (lane == 31) ws[w] = x;
    __syncthreads();
    if (w == 0 && lane < 8) {
        int y = ws[lane];
#pragma unroll
        for (int o = 1; o < 8; o <<= 1) {
            int z = __shfl_up_sync(0x000000ffu, y, o);
            if (lane >= o) y += z;
        }
        ws[lane] = y;
    }
    __syncthreads();
    if (t < NSCAN_BLOCKS) boff[t] = x - v + (w ? ws[w - 1] : 0);
}
__global__ __launch_bounds__(256) void scan3_k(int* __restrict__ rows,
                                               const int* __restrict__ boff,
                                               int* __restrict__ cur) {
    int i = blockIdx.x * 256 + threadIdx.x;
    if (i < N_NODES) {
        int r = rows[i] + boff[blockIdx.x];
        rows[i] = r;
        cur[i]  = r;
    }
    if (i == 0) rows[N_NODES] = N_EDGES;
}
__global__ void scatter_k(const int* __restrict__ src, const int* __restrict__ dst,
                          int* __restrict__ cur, int* __restrict__ csrc) {
    int e = blockIdx.x * blockDim.x + threadIdx.x;
    if (e < N_EDGES) {
        int pos = atomicAdd(&cur[dst[e]], 1);
        csrc[pos] = src[e];
    }
}

// ================= TF32 tensor-core GEMM (round-9 measured: 37us) =================
__device__ __forceinline__ unsigned f2tf(float f) {
    unsigned u;
    asm("cvt.rna.tf32.f32 %0, %1;" : "=r"(u) : "f"(f));
    return u;
}
__device__ __forceinline__ void mma_tf32(float c[4], const unsigned a[4], const unsigned b[2]) {
    asm volatile(
        "mma.sync.aligned.m16n8k8.row.col.f32.tf32.tf32.f32 "
        "{%0,%1,%2,%3}, {%4,%5,%6,%7}, {%8,%9}, {%0,%1,%2,%3};\n"
        : "+f"(c[0]), "+f"(c[1]), "+f"(c[2]), "+f"(c[3])
        : "r"(a[0]), "r"(a[1]), "r"(a[2]), "r"(a[3]), "r"(b[0]), "r"(b[1]));
}

#define GM 128
#define GN 128
#define GKB 16

__global__ __launch_bounds__(256, 2) void sgemm_tf32(const float* __restrict__ A,
                                                     const float* __restrict__ B,
                                                     float* __restrict__ C,
                                                     int M, int K) {
    __shared__ unsigned As[2][GM][20];    // [m][k], pad 20 -> conflict-free frag reads
    __shared__ unsigned Bs[2][GKB][136];  // [k][n], pad 136 -> (8k+n)%32 all distinct
    int tid  = threadIdx.x;
    int warp = tid >> 5, lane = tid & 31;
    int wm = warp >> 2, wn = warp & 3;          // 2 x 4 warp grid
    int rowBase = blockIdx.y * GM;
    int colBase = blockIdx.x * GN;
    int nk = K / GKB;

    int qr = lane >> 2, qc = lane & 3;          // mma quad coords

    int a_row0 = tid >> 2,        a_c0 = (tid & 3) * 4;
    int a_row1 = (tid >> 2) + 64, a_c1 = a_c0;
    int b_row0 = tid >> 5,        b_c0 = (tid & 31) * 4;
    int b_row1 = (tid >> 5) + 8;

    const float4 fz = make_float4(0.f, 0.f, 0.f, 0.f);
    float4 pa0, pa1, pb0, pb1;

    {
        int g0 = rowBase + a_row0, g1 = rowBase + a_row1;
        pa0 = (g0 < M) ? *(const float4*)(A + (long)g0 * K + a_c0) : fz;
        pa1 = (g1 < M) ? *(const float4*)(A + (long)g1 * K + a_c1) : fz;
        pb0 = *(const float4*)(B + (long)b_row0 * FDIM + colBase + b_c0);
        pb1 = *(const float4*)(B + (long)b_row1 * FDIM + colBase + b_c0);
    }
    {
        unsigned* pA0 = &As[0][a_row0][a_c0];
        pA0[0] = f2tf(pa0.x); pA0[1] = f2tf(pa0.y); pA0[2] = f2tf(pa0.z); pA0[3] = f2tf(pa0.w);
        unsigned* pA1 = &As[0][a_row1][a_c1];
        pA1[0] = f2tf(pa1.x); pA1[1] = f2tf(pa1.y); pA1[2] = f2tf(pa1.z); pA1[3] = f2tf(pa1.w);
        unsigned* pB0 = &Bs[0][b_row0][b_c0];
        pB0[0] = f2tf(pb0.x); pB0[1] = f2tf(pb0.y); pB0[2] = f2tf(pb0.z); pB0[3] = f2tf(pb0.w);
        unsigned* pB1 = &Bs[0][b_row1][b_c0];
        pB1[0] = f2tf(pb1.x); pB1[1] = f2tf(pb1.y); pB1[2] = f2tf(pb1.z); pB1[3] = f2tf(pb1.w);
    }
    __syncthreads();

    float cacc[4][4][4] = {};   // [mi][ni][frag]

    for (int kb = 0; kb < nk; kb++) {
        int nb = kb + 1;
        if (nb < nk) {
            int koff = nb * GKB;
            int g0 = rowBase + a_row0, g1 = rowBase + a_row1;
            pa0 = (g0 < M) ? *(const float4*)(A + (long)g0 * K + koff + a_c0) : fz;
            pa1 = (g1 < M) ? *(const float4*)(A + (long)g1 * K + koff + a_c1) : fz;
            pb0 = *(const float4*)(B + (long)(koff + b_row0) * FDIM + colBase + b_c0);
            pb1 = *(const float4*)(B + (long)(koff + b_row1) * FDIM + colBase + b_c0);
        }
        int cb = kb & 1;
#pragma unroll
        for (int ks = 0; ks < GKB; ks += 8) {
            unsigned af[4][4], bf[4][2];
#pragma unroll
            for (int mi = 0; mi < 4; mi++) {
                int r = wm * 64 + mi * 16 + qr;
                int c = ks + qc;
                af[mi][0] = As[cb][r][c];
                af[mi][1] = As[cb][r + 8][c];
                af[mi][2] = As[cb][r][c + 4];
                af[mi][3] = As[cb][r + 8][c + 4];
            }
#pragma unroll
            for (int ni = 0; ni < 4; ni++) {
                int n = wn * 32 + ni * 8 + qr;
                int k = ks + qc;
                bf[ni][0] = Bs[cb][k][n];
                bf[ni][1] = Bs[cb][k + 4][n];
            }
#pragma unroll
            for (int mi = 0; mi < 4; mi++)
#pragma unroll
                for (int ni = 0; ni < 4; ni++)
                    mma_tf32(cacc[mi][ni], af[mi], bf[ni]);
        }
        if (nb < nk) {
            int wb = nb & 1;
            unsigned* pA0 = &As[wb][a_row0][a_c0];
            pA0[0] = f2tf(pa0.x); pA0[1] = f2tf(pa0.y); pA0[2] = f2tf(pa0.z); pA0[3] = f2tf(pa0.w);
            unsigned* pA1 = &As[wb][a_row1][a_c1];
            pA1[0] = f2tf(pa1.x); pA1[1] = f2tf(pa1.y); pA1[2] = f2tf(pa1.z); pA1[3] = f2tf(pa1.w);
            unsigned* pB0 = &Bs[wb][b_row0][b_c0];
            pB0[0] = f2tf(pb0.x); pB0[1] = f2tf(pb0.y); pB0[2] = f2tf(pb0.z); pB0[3] = f2tf(pb0.w);
            unsigned* pB1 = &Bs[wb][b_row1][b_c0];
            pB1[0] = f2tf(pb1.x); pB1[1] = f2tf(pb1.y); pB1[2] = f2tf(pb1.z); pB1[3] = f2tf(pb1.w);
        }
        __syncthreads();
    }

#pragma unroll
    for (int mi = 0; mi < 4; mi++) {
        int r0 = rowBase + wm * 64 + mi * 16 + qr;
        int r1 = r0 + 8;
#pragma unroll
        for (int ni = 0; ni < 4; ni++) {
            int c = colBase + wn * 32 + ni * 8 + 2 * qc;
            if (r0 < M) {
                float2 v = make_float2(cacc[mi][ni][0], cacc[mi][ni][1]);
                *(float2*)(C + (long)r0 * FDIM + c) = v;
            }
            if (r1 < M) {
                float2 v = make_float2(cacc[mi][ni][2], cacc[mi][ni][3]);
                *(float2*)(C + (long)r1 * FDIM + c) = v;
            }
        }
    }
}

// ================= node prep: el/er =================
__global__ __launch_bounds__(256) void node_prep(const float* __restrict__ feat,
                                                 const float* __restrict__ al,
                                                 const float* __restrict__ ar,
                                                 float* __restrict__ el,
                                                 float* __restrict__ er) {
    int warp = (blockIdx.x * blockDim.x + threadIdx.x) >> 5;
    int lane = threadIdx.x & 31;
    if (warp >= N_NODES) return;
    const float* f = feat + (long)warp * FDIM;
#pragma unroll
    for (int h = 0; h < NHEAD; h++) {
        float v  = f[h * HIDD + lane];
        float pl = v * al[h * HIDD + lane];
        float pr = v * ar[h * HIDD + lane];
#pragma unroll
        for (int o = 16; o; o >>= 1) {
            pl += __shfl_down_sync(0xffffffffu, pl, o);
            pr += __shfl_down_sync(0xffffffffu, pr, o);
        }
        if (lane == 0) {
            el[warp * NHEAD + h] = pl;
            er[warp * NHEAD + h] = pr;
        }
    }
}

// ================= fused single-pass GAT aggregation (round-9 measured) =================
__global__ __launch_bounds__(256) void gat_aggr(const int* __restrict__ rows,
                                                const int* __restrict__ csrc,
                                                const float* __restrict__ el,
                                                const float* __restrict__ er,
                                                const float* __restrict__ feat,
                                                const float* __restrict__ hres,
                                                const float* __restrict__ bias,
                                                float* __restrict__ hout) {
    int tid  = threadIdx.x;
    int node = (blockIdx.x * blockDim.x + tid) >> 5;   // grid sized exactly -> always valid
    int lane = tid & 31;
    int myh  = lane >> 2;

    int e0 = rows[node], e1 = rows[node + 1];
    float er_my = er[node * NHEAD + myh];

    float acc[8] = {};
    float den = 0.f;
    const float4* f4 = (const float4*)feat;
    for (int e = e0; e < e1; e++) {
        int s = csrc[e];   // warp-uniform address: single broadcast load
        float v = __ldg(&el[s * NHEAD + myh]) + er_my;
        v = (v > 0.f) ? v : NEG_SLOPE * v;
        float a = __expf(v);
        den += a;
        float4 v0 = f4[(long)s * 64 + lane * 2];
        float4 v1 = f4[(long)s * 64 + lane * 2 + 1];
        acc[0] += a * v0.x; acc[1] += a * v0.y; acc[2] += a * v0.z; acc[3] += a * v0.w;
        acc[4] += a * v1.x; acc[5] += a * v1.y; acc[6] += a * v1.z; acc[7] += a * v1.w;
    }
    float inv = (den == 0.f) ? 1.f : 1.f / den;

    float4 b0 = ((const float4*)bias)[lane * 2];
    float4 b1 = ((const float4*)bias)[lane * 2 + 1];
    float bv[8] = {b0.x, b0.y, b0.z, b0.w, b1.x, b1.y, b1.z, b1.w};
    float rv[8] = {};
    if (hres) {
        float4 r0 = ((const float4*)(hres + (long)node * FDIM))[lane * 2];
        float4 r1 = ((const float4*)(hres + (long)node * FDIM))[lane * 2 + 1];
        rv[0] = r0.x; rv[1] = r0.y; rv[2] = r0.z; rv[3] = r0.w;
        rv[4] = r1.x; rv[5] = r1.y; rv[6] = r1.z; rv[7] = r1.w;
    }
    float o[8];
#pragma unroll
    for (int j = 0; j < 8; j++) {
        float val = acc[j] * inv + rv[j] + bv[j];
        o[j] = (val > 0.f) ? val : expm1f(val);
    }
    float* op = hout + (long)node * FDIM + lane * 8;
    *(float4*)op       = make_float4(o[0], o[1], o[2], o[3]);
    *(float4*)(op + 4) = make_float4(o[4], o[5], o[6], o[7]);
}

// ================= mean -> linear (commuted) =================
__global__ void zero_csum(float* c) { c[threadIdx.x] = 0.f; }

__global__ __launch_bounds__(256) void colsum_k(const float* __restrict__ h,
                                                float* __restrict__ csum) {
    int col = threadIdx.x;
    int r0 = blockIdx.x * 256;
    int r1 = min(r0 + 256, N_NODES);
    float s = 0.f;
    for (int r = r0; r < r1; r++) s += h[(long)r * FDIM + col];
    atomicAdd(&csum[col], s);
}

__global__ void final_k(const float* __restrict__ csum,
                        const float* __restrict__ Wl,
                        const float* __restrict__ bl,
                        float* __restrict__ out) {
    int j = threadIdx.x;
    float s = 0.f;
    for (int c = 0; c < FDIM; c++) s += csum[c] * Wl[c * 128 + j];
    out[j] = s * (1.f / (float)N_NODES) + bl[j];
}

// ================= host =================
extern "C" void kernel_launch(void* const* d_in, const int* in_sizes, int n_in,
                              void* d_out, int out_size) {
    const float* x   = (const float*)d_in[0];
    const int*   src = (const int*)  d_in[1];
    const int*   dst = (const int*)  d_in[2];
    const float* W1  = (const float*)d_in[3];
    const float* al1 = (const float*)d_in[4];
    const float* ar1 = (const float*)d_in[5];
    const float* b1  = (const float*)d_in[6];
    const float* W2  = (const float*)d_in[7];
    const float* al2 = (const float*)d_in[8];
    const float* ar2 = (const float*)d_in[9];
    const float* b2  = (const float*)d_in[10];
    const float* Wl  = (const float*)d_in[11];
    const float* bl  = (const float*)d_in[12];
    float* out = (float*)d_out;

    float *feat, *h1, *h2, *el, *er, *csum;
    int *cnt, *rows, *cur, *csrc, *bsum, *boff;
    cudaGetSymbolAddress((void**)&feat, g_feat);
    cudaGetSymbolAddress((void**)&h1,   g_h1);
    cudaGetSymbolAddress((void**)&h2,   g_h2);
    cudaGetSymbolAddress((void**)&el,   g_el);
    cudaGetSymbolAddress((void**)&er,   g_er);
    cudaGetSymbolAddress((void**)&csum, g_csum);
    cudaGetSymbolAddress((void**)&cnt,  g_cnt);
    cudaGetSymbolAddress((void**)&rows, g_rows);
    cudaGetSymbolAddress((void**)&cur,  g_cur);
    cudaGetSymbolAddress((void**)&csrc, g_csrc);
    cudaGetSymbolAddress((void**)&bsum, g_bsum);
    cudaGetSymbolAddress((void**)&boff, g_boff);

    int nodeBlocks     = (N_NODES + 255) / 256;     // 196
    int edgeBlocks     = (N_EDGES + 255) / 256;
    int nodeWarpBlocks = (N_NODES * 32) / 256;      // 6250 exact
    dim3 gemm_grid(FDIM / GN, (N_NODES + GM - 1) / GM);

    // CSR build + layer-1 projection (sgemm is 4th launch -> profiled)
    zero_cnt<<<nodeBlocks, 256>>>(cnt);
    hist_k<<<edgeBlocks, 256>>>(dst, cnt);
    scan1_k<<<nodeBlocks, 256>>>(cnt, rows, bsum);
    sgemm_tf32<<<gemm_grid, 256>>>(x, W1, feat, N_NODES, 128);
    scan2_k<<<1, 256>>>(bsum, boff);
    scan3_k<<<nodeBlocks, 256>>>(rows, boff, cur);
    scatter_k<<<edgeBlocks, 256>>>(src, dst, cur, csrc);

    // layer 1 (no residual)
    node_prep<<<nodeWarpBlocks, 256>>>(feat, al1, ar1, el, er);
    gat_aggr<<<nodeWarpBlocks, 256>>>(rows, csrc, el, er, feat, nullptr, b1, h1);

    // layer 2 (identity residual)
    sgemm_tf32<<<gemm_grid, 256>>>(h1, W2, feat, N_NODES, 256);
    node_prep<<<nodeWarpBlocks, 256>>>(feat, al2, ar2, el, er);
    gat_aggr<<<nodeWarpBlocks, 256>>>(rows, csrc, el, er, feat, h1, b2, h2);

    // out = colmean(h2) @ Wl + bl
    zero_csum<<<1, FDIM>>>(csum);
    colsum_k<<<nodeBlocks, 256>>>(h2, csum);
    final_k<<<1, 128>>>(csum, Wl, bl, out);
}

// round 12
// speedup vs baseline: 1.4528x; 1.1383x over previous
#include <cuda_runtime.h>
#include <cuda_bf16.h>
#include <math.h>

#define N_NODES 50000
#define N_EDGES 800000
#define NHEAD 8
#define HIDD 32
#define FDIM 256
#define NEG_SLOPE 0.2f
#define NSCAN_BLOCKS 196   /* ceil(50000/256) */

// ---------------- scratch ----------------
__device__ float          g_feat [N_NODES * FDIM];
__device__ __nv_bfloat16  g_featb[N_NODES * FDIM];   // bf16 gather copy
__device__ float          g_h1   [N_NODES * FDIM];
__device__ float          g_el   [N_NODES * NHEAD];
__device__ float          g_er   [N_NODES * NHEAD];
__device__ float          g_csum [FDIM];
__device__ int            g_cnt  [N_NODES];
__device__ int            g_rows [N_NODES + 1];
__device__ int            g_cur  [N_NODES];
__device__ int            g_csrc [N_EDGES];
__device__ int            g_bsum [NSCAN_BLOCKS];
__device__ int            g_boff [NSCAN_BLOCKS];

// ================= CSR build =================
__global__ void zero_cnt(int* cnt) {
    int i = blockIdx.x * blockDim.x + threadIdx.x;
    if (i < N_NODES) cnt[i] = 0;
}
__global__ void hist_k(const int* __restrict__ dst, int* __restrict__ cnt) {
    int e = blockIdx.x * blockDim.x + threadIdx.x;
    if (e < N_EDGES) atomicAdd(&cnt[dst[e]], 1);
}
__global__ __launch_bounds__(256) void scan1_k(const int* __restrict__ cnt,
                                               int* __restrict__ rows,
                                               int* __restrict__ bsum) {
    __shared__ int ws[8];
    int t = threadIdx.x, lane = t & 31, w = t >> 5;
    int i = blockIdx.x * 256 + t;
    int v = (i < N_NODES) ? cnt[i] : 0;
    int x = v;
#pragma unroll
    for (int o = 1; o < 32; o <<= 1) {
        int y = __shfl_up_sync(0xffffffffu, x, o);
        if (lane >= o) x += y;
    }
    if (lane == 31) ws[w] = x;
    __syncthreads();
    if (w == 0 && lane < 8) {
        int y = ws[lane];
#pragma unroll
        for (int o = 1; o < 8; o <<= 1) {
            int z = __shfl_up_sync(0x000000ffu, y, o);
            if (lane >= o) y += z;
        }
        ws[lane] = y;
    }
    __syncthreads();
    int excl = x - v + (w ? ws[w - 1] : 0);
    if (i < N_NODES) rows[i] = excl;
    if (t == 255) bsum[blockIdx.x] = excl + v;
}
__global__ __launch_bounds__(256) void scan2_k(const int* __restrict__ bsum,
                                               int* __restrict__ boff) {
    __shared__ int ws[8];
    int t = threadIdx.x, lane = t & 31, w = t >> 5;
    int v = (t < NSCAN_BLOCKS) ? bsum[t] : 0;
    int x = v;
#pragma unroll
    for (int o = 1; o < 32; o <<= 1) {
        int y = __shfl_up_sync(0xffffffffu, x, o);
        if (lane >= o) x += y;
    }
    if (lane == 31) ws[w] = x;
    __syncthreads();
    if (w == 0 && lane < 8) {
        int y = ws[lane];
#pragma unroll
        for (int o = 1; o < 8; o <<= 1) {
            int z = __shfl_up_sync(0x000000ffu, y, o);
            if (lane >= o) y += z;
        }
        ws[lane] = y;
    }
    __syncthreads();
    if (t < NSCAN_BLOCKS) boff[t] = x - v + (w ? ws[w - 1] : 0);
}
__global__ __launch_bounds__(256) void scan3_k(int* __restrict__ rows,
                                               const int* __restrict__ boff,
                                               int* __restrict__ cur) {
    int i = blockIdx.x * 256 + threadIdx.x;
    if (i < N_NODES) {
        int r = rows[i] + boff[blockIdx.x];
        rows[i] = r;
        cur[i]  = r;
    }
    if (i == 0) rows[N_NODES] = N_EDGES;
}
__global__ void scatter_k(const int* __restrict__ src, const int* __restrict__ dst,
                          int* __restrict__ cur, int* __restrict__ csrc) {
    int e = blockIdx.x * blockDim.x + threadIdx.x;
    if (e < N_EDGES) {
        int pos = atomicAdd(&cur[dst[e]], 1);
        csrc[pos] = src[e];
    }
}

// ================= TF32 tensor-core GEMM (measured: 37us @K=128) =================
__device__ __forceinline__ unsigned f2tf(float f) {
    unsigned u;
    asm("cvt.rna.tf32.f32 %0, %1;" : "=r"(u) : "f"(f));
    return u;
}
__device__ __forceinline__ void mma_tf32(float c[4], const unsigned a[4], const unsigned b[2]) {
    asm volatile(
        "mma.sync.aligned.m16n8k8.row.col.f32.tf32.tf32.f32 "
        "{%0,%1,%2,%3}, {%4,%5,%6,%7}, {%8,%9}, {%0,%1,%2,%3};\n"
        : "+f"(c[0]), "+f"(c[1]), "+f"(c[2]), "+f"(c[3])
        : "r"(a[0]), "r"(a[1]), "r"(a[2]), "r"(a[3]), "r"(b[0]), "r"(b[1]));
}

#define GM 128
#define GN 128
#define GKB 16

__global__ __launch_bounds__(256, 2) void sgemm_tf32(const float* __restrict__ A,
                                                     const float* __restrict__ B,
                                                     float* __restrict__ C,
                                                     int M, int K) {
    __shared__ unsigned As[2][GM][20];
    __shared__ unsigned Bs[2][GKB][136];
    int tid  = threadIdx.x;
    int warp = tid >> 5, lane = tid & 31;
    int wm = warp >> 2, wn = warp & 3;
    int rowBase = blockIdx.y * GM;
    int colBase = blockIdx.x * GN;
    int nk = K / GKB;

    int qr = lane >> 2, qc = lane & 3;

    int a_row0 = tid >> 2,        a_c0 = (tid & 3) * 4;
    int a_row1 = (tid >> 2) + 64, a_c1 = a_c0;
    int b_row0 = tid >> 5,        b_c0 = (tid & 31) * 4;
    int b_row1 = (tid >> 5) + 8;

    const float4 fz = make_float4(0.f, 0.f, 0.f, 0.f);
    float4 pa0, pa1, pb0, pb1;

    {
        int g0 = rowBase + a_row0, g1 = rowBase + a_row1;
        pa0 = (g0 < M) ? *(const float4*)(A + (long)g0 * K + a_c0) : fz;
        pa1 = (g1 < M) ? *(const float4*)(A + (long)g1 * K + a_c1) : fz;
        pb0 = *(const float4*)(B + (long)b_row0 * FDIM + colBase + b_c0);
        pb1 = *(const float4*)(B + (long)b_row1 * FDIM + colBase + b_c0);
    }
    {
        unsigned* pA0 = &As[0][a_row0][a_c0];
        pA0[0] = f2tf(pa0.x); pA0[1] = f2tf(pa0.y); pA0[2] = f2tf(pa0.z); pA0[3] = f2tf(pa0.w);
        unsigned* pA1 = &As[0][a_row1][a_c1];
        pA1[0] = f2tf(pa1.x); pA1[1] = f2tf(pa1.y); pA1[2] = f2tf(pa1.z); pA1[3] = f2tf(pa1.w);
        unsigned* pB0 = &Bs[0][b_row0][b_c0];
        pB0[0] = f2tf(pb0.x); pB0[1] = f2tf(pb0.y); pB0[2] = f2tf(pb0.z); pB0[3] = f2tf(pb0.w);
        unsigned* pB1 = &Bs[0][b_row1][b_c0];
        pB1[0] = f2tf(pb1.x); pB1[1] = f2tf(pb1.y); pB1[2] = f2tf(pb1.z); pB1[3] = f2tf(pb1.w);
    }
    __syncthreads();

    float cacc[4][4][4] = {};

    for (int kb = 0; kb < nk; kb++) {
        int nb = kb + 1;
        if (nb < nk) {
            int koff = nb * GKB;
            int g0 = rowBase + a_row0, g1 = rowBase + a_row1;
            pa0 = (g0 < M) ? *(const float4*)(A + (long)g0 * K + koff + a_c0) : fz;
            pa1 = (g1 < M) ? *(const float4*)(A + (long)g1 * K + koff + a_c1) : fz;
            pb0 = *(const float4*)(B + (long)(koff + b_row0) * FDIM + colBase + b_c0);
            pb1 = *(const float4*)(B + (long)(koff + b_row1) * FDIM + colBase + b_c0);
        }
        int cb = kb & 1;
#pragma unroll
        for (int ks = 0; ks < GKB; ks += 8) {
            unsigned af[4][4], bf[4][2];
#pragma unroll
            for (int mi = 0; mi < 4; mi++) {
                int r = wm * 64 + mi * 16 + qr;
                int c = ks + qc;
                af[mi][0] = As[cb][r][c];
                af[mi][1] = As[cb][r + 8][c];
                af[mi][2] = As[cb][r][c + 4];
                af[mi][3] = As[cb][r + 8][c + 4];
            }
#pragma unroll
            for (int ni = 0; ni < 4; ni++) {
                int n = wn * 32 + ni * 8 + qr;
                int k = ks + qc;
                bf[ni][0] = Bs[cb][k][n];
                bf[ni][1] = Bs[cb][k + 4][n];
            }
#pragma unroll
            for (int mi = 0; mi < 4; mi++)
#pragma unroll
                for (int ni = 0; ni < 4; ni++)
                    mma_tf32(cacc[mi][ni], af[mi], bf[ni]);
        }
        if (nb < nk) {
            int wb = nb & 1;
            unsigned* pA0 = &As[wb][a_row0][a_c0];
            pA0[0] = f2tf(pa0.x); pA0[1] = f2tf(pa0.y); pA0[2] = f2tf(pa0.z); pA0[3] = f2tf(pa0.w);
            unsigned* pA1 = &As[wb][a_row1][a_c1];
            pA1[0] = f2tf(pa1.x); pA1[1] = f2tf(pa1.y); pA1[2] = f2tf(pa1.z); pA1[3] = f2tf(pa1.w);
            unsigned* pB0 = &Bs[wb][b_row0][b_c0];
            pB0[0] = f2tf(pb0.x); pB0[1] = f2tf(pb0.y); pB0[2] = f2tf(pb0.z); pB0[3] = f2tf(pb0.w);
            unsigned* pB1 = &Bs[wb][b_row1][b_c0];
            pB1[0] = f2tf(pb1.x); pB1[1] = f2tf(pb1.y); pB1[2] = f2tf(pb1.z); pB1[3] = f2tf(pb1.w);
        }
        __syncthreads();
    }

#pragma unroll
    for (int mi = 0; mi < 4; mi++) {
        int r0 = rowBase + wm * 64 + mi * 16 + qr;
        int r1 = r0 + 8;
#pragma unroll
        for (int ni = 0; ni < 4; ni++) {
            int c = colBase + wn * 32 + ni * 8 + 2 * qc;
            if (r0 < M) {
                float2 v = make_float2(cacc[mi][ni][0], cacc[mi][ni][1]);
                *(float2*)(C + (long)r0 * FDIM + c) = v;
            }
            if (r1 < M) {
                float2 v = make_float2(cacc[mi][ni][2], cacc[mi][ni][3]);
                *(float2*)(C + (long)r1 * FDIM + c) = v;
            }
        }
    }
}

// ================= node prep: el/er + bf16 feat copy =================
__global__ __launch_bounds__(256) void node_prep(const float* __restrict__ feat,
                                                 const float* __restrict__ al,
                                                 const float* __restrict__ ar,
                                                 float* __restrict__ el,
                                                 float* __restrict__ er,
                                                 __nv_bfloat16* __restrict__ featb) {
    int warp = (blockIdx.x * blockDim.x + threadIdx.x) >> 5;
    int lane = threadIdx.x & 31;
    if (warp >= N_NODES) return;
    const float* f = feat + (long)warp * FDIM;
    __nv_bfloat16* fb = featb + (long)warp * FDIM;
#pragma unroll
    for (int h = 0; h < NHEAD; h++) {
        float v  = f[h * HIDD + lane];
        fb[h * HIDD + lane] = __float2bfloat16(v);
        float pl = v * al[h * HIDD + lane];
        float pr = v * ar[h * HIDD + lane];
#pragma unroll
        for (int o = 16; o; o >>= 1) {
            pl += __shfl_down_sync(0xffffffffu, pl, o);
            pr += __shfl_down_sync(0xffffffffu, pr, o);
        }
        if (lane == 0) {
            el[warp * NHEAD + h] = pl;
            er[warp * NHEAD + h] = pr;
        }
    }
}

// ================= fused single-pass GAT aggregation, bf16 gather =================
// one warp per dst node; lane owns cols [lane*8, lane*8+8); head = lane>>2.
// mode hout!=null: write per-node row. mode hout==null: block-reduce into csum.
__global__ __launch_bounds__(256) void gat_aggr(const int* __restrict__ rows,
                                                const int* __restrict__ csrc,
                                                const float* __restrict__ el,
                                                const float* __restrict__ er,
                                                const __nv_bfloat16* __restrict__ featb,
                                                const float* __restrict__ hres,
                                                const float* __restrict__ bias,
                                                float* __restrict__ hout,
                                                float* __restrict__ csum) {
    __shared__ float ssum[8][FDIM];
    int tid  = threadIdx.x;
    int node = (blockIdx.x * blockDim.x + tid) >> 5;   // grid sized exactly -> always valid
    int lane = tid & 31;
    int w    = tid >> 5;
    int myh  = lane >> 2;

    int e0 = rows[node], e1 = rows[node + 1];
    float er_my = er[node * NHEAD + myh];

    float acc[8] = {};
    float den = 0.f;
    const uint4* fb4 = (const uint4*)featb;            // 8 bf16 per uint4; 32 per row
    for (int e = e0; e < e1; e++) {
        int s = csrc[e];                               // warp-uniform broadcast load
        float v = __ldg(&el[s * NHEAD + myh]) + er_my;
        v = (v > 0.f) ? v : NEG_SLOPE * v;
        float a = __expf(v);
        den += a;
        uint4 q = fb4[(long)s * 32 + lane];            // cols [lane*8, lane*8+8)
        float2 p0 = __bfloat1622float2(*reinterpret_cast<__nv_bfloat162*>(&q.x));
        float2 p1 = __bfloat1622float2(*reinterpret_cast<__nv_bfloat162*>(&q.y));
        float2 p2 = __bfloat1622float2(*reinterpret_cast<__nv_bfloat162*>(&q.z));
        float2 p3 = __bfloat1622float2(*reinterpret_cast<__nv_bfloat162*>(&q.w));
        acc[0] += a * p0.x; acc[1] += a * p0.y;
        acc[2] += a * p1.x; acc[3] += a * p1.y;
        acc[4] += a * p2.x; acc[5] += a * p2.y;
        acc[6] += a * p3.x; acc[7] += a * p3.y;
    }
    float inv = (den == 0.f) ? 1.f : 1.f / den;

    float4 b0 = ((const float4*)bias)[lane * 2];
    float4 b1 = ((const float4*)bias)[lane * 2 + 1];
    float bv[8] = {b0.x, b0.y, b0.z, b0.w, b1.x, b1.y, b1.z, b1.w};
    float rv[8] = {};
    if (hres) {
        float4 r0 = ((const float4*)(hres + (long)node * FDIM))[lane * 2];
        float4 r1 = ((const float4*)(hres + (long)node * FDIM))[lane * 2 + 1];
        rv[0] = r0.x; rv[1] = r0.y; rv[2] = r0.z; rv[3] = r0.w;
        rv[4] = r1.x; rv[5] = r1.y; rv[6] = r1.z; rv[7] = r1.w;
    }
    float o[8];
#pragma unroll
    for (int j = 0; j < 8; j++) {
        float val = acc[j] * inv + rv[j] + bv[j];
        o[j] = (val > 0.f) ? val : expm1f(val);
    }
    if (hout) {
        float* op = hout + (long)node * FDIM + lane * 8;
        *(float4*)op       = make_float4(o[0], o[1], o[2], o[3]);
        *(float4*)(op + 4) = make_float4(o[4], o[5], o[6], o[7]);
    } else {
        // per-warp row in smem (plain stores), tree-sum, 256 global atomics/block
        *(float4*)&ssum[w][lane * 8]     = make_float4(o[0], o[1], o[2], o[3]);
        *(float4*)&ssum[w][lane * 8 + 4] = make_float4(o[4], o[5], o[6], o[7]);
        __syncthreads();
        float s = 0.f;
#pragma unroll
        for (int ww = 0; ww < 8; ww++) s += ssum[ww][tid];
        atomicAdd(&csum[tid], s);
    }
}

// ================= final GEMV (mean commuted through linear) =================
__global__ void zero_csum(float* c) { c[threadIdx.x] = 0.f; }

__global__ void final_k(const float* __restrict__ csum,
                        const float* __restrict__ Wl,
                        const float* __restrict__ bl,
                        float* __restrict__ out) {
    int j = threadIdx.x;
    float s = 0.f;
    for (int c = 0; c < FDIM; c++) s += csum[c] * Wl[c * 128 + j];
    out[j] = s * (1.f / (float)N_NODES) + bl[j];
}

// ================= host =================
extern "C" void kernel_launch(void* const* d_in, const int* in_sizes, int n_in,
                              void* d_out, int out_size) {
    const float* x   = (const float*)d_in[0];
    const int*   src = (const int*)  d_in[1];
    const int*   dst = (const int*)  d_in[2];
    const float* W1  = (const float*)d_in[3];
    const float* al1 = (const float*)d_in[4];
    const float* ar1 = (const float*)d_in[5];
    const float* b1  = (const float*)d_in[6];
    const float* W2  = (const float*)d_in[7];
    const float* al2 = (const float*)d_in[8];
    const float* ar2 = (const float*)d_in[9];
    const float* b2  = (const float*)d_in[10];
    const float* Wl  = (const float*)d_in[11];
    const float* bl  = (const float*)d_in[12];
    float* out = (float*)d_out;

    float *feat, *h1, *el, *er, *csum;
    __nv_bfloat16* featb;
    int *cnt, *rows, *cur, *csrc, *bsum, *boff;
    cudaGetSymbolAddress((void**)&feat,  g_feat);
    cudaGetSymbolAddress((void**)&featb, g_featb);
    cudaGetSymbolAddress((void**)&h1,    g_h1);
    cudaGetSymbolAddress((void**)&el,    g_el);
    cudaGetSymbolAddress((void**)&er,    g_er);
    cudaGetSymbolAddress((void**)&csum,  g_csum);
    cudaGetSymbolAddress((void**)&cnt,   g_cnt);
    cudaGetSymbolAddress((void**)&rows,  g_rows);
    cudaGetSymbolAddress((void**)&cur,   g_cur);
    cudaGetSymbolAddress((void**)&csrc,  g_csrc);
    cudaGetSymbolAddress((void**)&bsum,  g_bsum);
    cudaGetSymbolAddress((void**)&boff,  g_boff);

    int nodeBlocks     = (N_NODES + 255) / 256;     // 196
    int edgeBlocks     = (N_EDGES + 255) / 256;
    int nodeWarpBlocks = (N_NODES * 32) / 256;      // 6250 exact
    dim3 gemm_grid(FDIM / GN, (N_NODES + GM - 1) / GM);

    // CSR build + layer-1 projection (sgemm stays the 4th launch -> profiled)
    zero_cnt<<<nodeBlocks, 256>>>(cnt);
    hist_k<<<edgeBlocks, 256>>>(dst, cnt);
    scan1_k<<<nodeBlocks, 256>>>(cnt, rows, bsum);
    sgemm_tf32<<<gemm_grid, 256>>>(x, W1, feat, N_NODES, 128);
    scan2_k<<<1, 256>>>(bsum, boff);
    scan3_k<<<nodeBlocks, 256>>>(rows, boff, cur);
    scatter_k<<<edgeBlocks, 256>>>(src, dst, cur, csrc);

    // layer 1 (no residual)
    node_prep<<<nodeWarpBlocks, 256>>>(feat, al1, ar1, el, er, featb);
    gat_aggr<<<nodeWarpBlocks, 256>>>(rows, csrc, el, er, featb, nullptr, b1, h1, nullptr);

    // layer 2 (identity residual) — output block-reduced straight into csum
    sgemm_tf32<<<gemm_grid, 256>>>(h1, W2, feat, N_NODES, 256);
    node_prep<<<nodeWarpBlocks, 256>>>(feat, al2, ar2, el, er, featb);
    zero_csum<<<1, FDIM>>>(csum);
    gat_aggr<<<nodeWarpBlocks, 256>>>(rows, csrc, el, er, featb, h1, b2, nullptr, csum);

    // out = colmean(h2) @ Wl + bl
    final_k<<<1, 128>>>(csum, Wl, bl, out);
}

// round 13
// speedup vs baseline: 1.6434x; 1.1313x over previous
#include <cuda_runtime.h>
#include <cuda_bf16.h>
#include <math.h>

#define N_NODES 50000
#define N_EDGES 800000
#define NHEAD 8
#define HIDD 32
#define FDIM 256
#define NEG_SLOPE 0.2f
#define NSCAN_BLOCKS 196   /* ceil(50000/256) */

// ---------------- scratch ----------------
__device__ __nv_bfloat16  g_featb[N_NODES * FDIM];   // projected features (bf16)
__device__ float          g_h1   [N_NODES * FDIM];   // layer-1 output (fp32: residual + GEMM2 input)
__device__ float          g_el   [N_NODES * NHEAD];
__device__ float          g_er   [N_NODES * NHEAD];
__device__ float          g_csum [FDIM];
__device__ int            g_cnt  [N_NODES];
__device__ int            g_rows [N_NODES + 1];
__device__ int            g_cur  [N_NODES];
__device__ int            g_csrc [N_EDGES];
__device__ int            g_bsum [NSCAN_BLOCKS];
__device__ int            g_boff [NSCAN_BLOCKS];

// ================= CSR build =================
__global__ void zero_cnt(int* cnt) {
    int i = blockIdx.x * blockDim.x + threadIdx.x;
    if (i < N_NODES) cnt[i] = 0;
}
__global__ void hist_k(const int* __restrict__ dst, int* __restrict__ cnt) {
    int e = blockIdx.x * blockDim.x + threadIdx.x;
    if (e < N_EDGES) atomicAdd(&cnt[dst[e]], 1);
}
__global__ __launch_bounds__(256) void scan1_k(const int* __restrict__ cnt,
                                               int* __restrict__ rows,
                                               int* __restrict__ bsum) {
    __shared__ int ws[8];
    int t = threadIdx.x, lane = t & 31, w = t >> 5;
    int i = blockIdx.x * 256 + t;
    int v = (i < N_NODES) ? cnt[i] : 0;
    int x = v;
#pragma unroll
    for (int o = 1; o < 32; o <<= 1) {
        int y = __shfl_up_sync(0xffffffffu, x, o);
        if (lane >= o) x += y;
    }
    if (lane == 31) ws[w] = x;
    __syncthreads();
    if (w == 0 && lane < 8) {
        int y = ws[lane];
#pragma unroll
        for (int o = 1; o < 8; o <<= 1) {
            int z = __shfl_up_sync(0x000000ffu, y, o);
            if (lane >= o) y += z;
        }
        ws[lane] = y;
    }
    __syncthreads();
    int excl = x - v + (w ? ws[w - 1] : 0);
    if (i < N_NODES) rows[i] = excl;
    if (t == 255) bsum[blockIdx.x] = excl + v;
}
__global__ __launch_bounds__(256) void scan2_k(const int* __restrict__ bsum,
                                               int* __restrict__ boff) {
    __shared__ int ws[8];
    int t = threadIdx.x, lane = t & 31, w = t >> 5;
    int v = (t < NSCAN_BLOCKS) ? bsum[t] : 0;
    int x = v;
#pragma unroll
    for (int o = 1; o < 32; o <<= 1) {
        int y = __shfl_up_sync(0xffffffffu, x, o);
        if (lane >= o) x += y;
    }
    if (lane == 31) ws[w] = x;
    __syncthreads();
    if (w == 0 && lane < 8) {
        int y = ws[lane];
#pragma unroll
        for (int o = 1; o < 8; o <<= 1) {
            int z = __shfl_up_sync(0x000000ffu, y, o);
            if (lane >= o) y += z;
        }
        ws[lane] = y;
    }
    __syncthreads();
    if (t < NSCAN_BLOCKS) boff[t] = x - v + (w ? ws[w - 1] : 0);
}
__global__ __launch_bounds__(256) void scan3_k(int* __restrict__ rows,
                                               const int* __restrict__ boff,
                                               int* __restrict__ cur) {
    int i = blockIdx.x * 256 + threadIdx.x;
    if (i < N_NODES) {
        int r = rows[i] + boff[blockIdx.x];
        rows[i] = r;
        cur[i]  = r;
    }
    if (i == 0) rows[N_NODES] = N_EDGES;
}
__global__ void scatter_k(const int* __restrict__ src, const int* __restrict__ dst,
                          int* __restrict__ cur, int* __restrict__ csrc) {
    int e = blockIdx.x * blockDim.x + threadIdx.x;
    if (e < N_EDGES) {
        int pos = atomicAdd(&cur[dst[e]], 1);
        csrc[pos] = src[e];
    }
}

// ================= TF32 tensor-core GEMM, bf16 output =================
__device__ __forceinline__ unsigned f2tf(float f) {
    unsigned u;
    asm("cvt.rna.tf32.f32 %0, %1;" : "=r"(u) : "f"(f));
    return u;
}
__device__ __forceinline__ void mma_tf32(float c[4], const unsigned a[4], const unsigned b[2]) {
    asm volatile(
        "mma.sync.aligned.m16n8k8.row.col.f32.tf32.tf32.f32 "
        "{%0,%1,%2,%3}, {%4,%5,%6,%7}, {%8,%9}, {%0,%1,%2,%3};\n"
        : "+f"(c[0]), "+f"(c[1]), "+f"(c[2]), "+f"(c[3])
        : "r"(a[0]), "r"(a[1]), "r"(a[2]), "r"(a[3]), "r"(b[0]), "r"(b[1]));
}

#define GM 128
#define GN 128
#define GKB 16

__global__ __launch_bounds__(256, 2) void sgemm_tf32(const float* __restrict__ A,
                                                     const float* __restrict__ B,
                                                     __nv_bfloat16* __restrict__ Cb,
                                                     int M, int K) {
    __shared__ unsigned As[2][GM][20];
    __shared__ unsigned Bs[2][GKB][136];
    int tid  = threadIdx.x;
    int warp = tid >> 5, lane = tid & 31;
    int wm = warp >> 2, wn = warp & 3;
    int rowBase = blockIdx.y * GM;
    int colBase = blockIdx.x * GN;
    int nk = K / GKB;

    int qr = lane >> 2, qc = lane & 3;

    int a_row0 = tid >> 2,        a_c0 = (tid & 3) * 4;
    int a_row1 = (tid >> 2) + 64, a_c1 = a_c0;
    int b_row0 = tid >> 5,        b_c0 = (tid & 31) * 4;
    int b_row1 = (tid >> 5) + 8;

    const float4 fz = make_float4(0.f, 0.f, 0.f, 0.f);
    float4 pa0, pa1, pb0, pb1;

    {
        int g0 = rowBase + a_row0, g1 = rowBase + a_row1;
        pa0 = (g0 < M) ? *(const float4*)(A + (long)g0 * K + a_c0) : fz;
        pa1 = (g1 < M) ? *(const float4*)(A + (long)g1 * K + a_c1) : fz;
        pb0 = *(const float4*)(B + (long)b_row0 * FDIM + colBase + b_c0);
        pb1 = *(const float4*)(B + (long)b_row1 * FDIM + colBase + b_c0);
    }
    {
        unsigned* pA0 = &As[0][a_row0][a_c0];
        pA0[0] = f2tf(pa0.x); pA0[1] = f2tf(pa0.y); pA0[2] = f2tf(pa0.z); pA0[3] = f2tf(pa0.w);
        unsigned* pA1 = &As[0][a_row1][a_c1];
        pA1[0] = f2tf(pa1.x); pA1[1] = f2tf(pa1.y); pA1[2] = f2tf(pa1.z); pA1[3] = f2tf(pa1.w);
        unsigned* pB0 = &Bs[0][b_row0][b_c0];
        pB0[0] = f2tf(pb0.x); pB0[1] = f2tf(pb0.y); pB0[2] = f2tf(pb0.z); pB0[3] = f2tf(pb0.w);
        unsigned* pB1 = &Bs[0][b_row1][b_c0];
        pB1[0] = f2tf(pb1.x); pB1[1] = f2tf(pb1.y); pB1[2] = f2tf(pb1.z); pB1[3] = f2tf(pb1.w);
    }
    __syncthreads();

    float cacc[4][4][4] = {};

    for (int kb = 0; kb < nk; kb++) {
        int nb = kb + 1;
        if (nb < nk) {
            int koff = nb * GKB;
            int g0 = rowBase + a_row0, g1 = rowBase + a_row1;
            pa0 = (g0 < M) ? *(const float4*)(A + (long)g0 * K + koff + a_c0) : fz;
            pa1 = (g1 < M) ? *(const float4*)(A + (long)g1 * K + koff + a_c1) : fz;
            pb0 = *(const float4*)(B + (long)(koff + b_row0) * FDIM + colBase + b_c0);
            pb1 = *(const float4*)(B + (long)(koff + b_row1) * FDIM + colBase + b_c0);
        }
        int cb = kb & 1;
#pragma unroll
        for (int ks = 0; ks < GKB; ks += 8) {
            unsigned af[4][4], bf[4][2];
#pragma unroll
            for (int mi = 0; mi < 4; mi++) {
                int r = wm * 64 + mi * 16 + qr;
                int c = ks + qc;
                af[mi][0] = As[cb][r][c];
                af[mi][1] = As[cb][r + 8][c];
                af[mi][2] = As[cb][r][c + 4];
                af[mi][3] = As[cb][r + 8][c + 4];
            }
#pragma unroll
            for (int ni = 0; ni < 4; ni++) {
                int n = wn * 32 + ni * 8 + qr;
                int k = ks + qc;
                bf[ni][0] = Bs[cb][k][n];
                bf[ni][1] = Bs[cb][k + 4][n];
            }
#pragma unroll
            for (int mi = 0; mi < 4; mi++)
#pragma unroll
                for (int ni = 0; ni < 4; ni++)
                    mma_tf32(cacc[mi][ni], af[mi], bf[ni]);
        }
        if (nb < nk) {
            int wb = nb & 1;
            unsigned* pA0 = &As[wb][a_row0][a_c0];
            pA0[0] = f2tf(pa0.x); pA0[1] = f2tf(pa0.y); pA0[2] = f2tf(pa0.z); pA0[3] = f2tf(pa0.w);
            unsigned* pA1 = &As[wb][a_row1][a_c1];
            pA1[0] = f2tf(pa1.x); pA1[1] = f2tf(pa1.y); pA1[2] = f2tf(pa1.z); pA1[3] = f2tf(pa1.w);
            unsigned* pB0 = &Bs[wb][b_row0][b_c0];
            pB0[0] = f2tf(pb0.x); pB0[1] = f2tf(pb0.y); pB0[2] = f2tf(pb0.z); pB0[3] = f2tf(pb0.w);
            unsigned* pB1 = &Bs[wb][b_row1][b_c0];
            pB1[0] = f2tf(pb1.x); pB1[1] = f2tf(pb1.y); pB1[2] = f2tf(pb1.z); pB1[3] = f2tf(pb1.w);
        }
        __syncthreads();
    }

    // store C as bf16 (4B stores, rounded from fp32 accum)
#pragma unroll
    for (int mi = 0; mi < 4; mi++) {
        int r0 = rowBase + wm * 64 + mi * 16 + qr;
        int r1 = r0 + 8;
#pragma unroll
        for (int ni = 0; ni < 4; ni++) {
            int c = colBase + wn * 32 + ni * 8 + 2 * qc;
            if (r0 < M) {
                *(__nv_bfloat162*)(Cb + (long)r0 * FDIM + c) =
                    __float22bfloat162_rn(make_float2(cacc[mi][ni][0], cacc[mi][ni][1]));
            }
            if (r1 < M) {
                *(__nv_bfloat162*)(Cb + (long)r1 * FDIM + c) =
                    __float22bfloat162_rn(make_float2(cacc[mi][ni][2], cacc[mi][ni][3]));
            }
        }
    }
}

// ================= node prep: el/er from bf16 feat (one uint4/lane) =================
// lane owns cols [lane*8, lane*8+8) == 8 cols of head myh = lane>>2.
__global__ __launch_bounds__(256) void node_prep(const __nv_bfloat16* __restrict__ featb,
                                                 const float* __restrict__ al,
                                                 const float* __restrict__ ar,
                                                 float* __restrict__ el,
                                                 float* __restrict__ er) {
    int node = (blockIdx.x * blockDim.x + threadIdx.x) >> 5;  // grid exact
    int lane = threadIdx.x & 31;
    int myh = lane >> 2, sub = lane & 3;

    uint4 q = ((const uint4*)featb)[(long)node * 32 + lane];
    float2 p0 = __bfloat1622float2(*reinterpret_cast<__nv_bfloat162*>(&q.x));
    float2 p1 = __bfloat1622float2(*reinterpret_cast<__nv_bfloat162*>(&q.y));
    float2 p2 = __bfloat1622float2(*reinterpret_cast<__nv_bfloat162*>(&q.z));
    float2 p3 = __bfloat1622float2(*reinterpret_cast<__nv_bfloat162*>(&q.w));

    const float4* al4 = (const float4*)(al + myh * HIDD + sub * 8);
    const float4* ar4 = (const float4*)(ar + myh * HIDD + sub * 8);
    float4 a0 = al4[0], a1 = al4[1];
    float4 r0 = ar4[0], r1 = ar4[1];

    float pl = p0.x * a0.x + p0.y * a0.y + p1.x * a0.z + p1.y * a0.w
             + p2.x * a1.x + p2.y * a1.y + p3.x * a1.z + p3.y * a1.w;
    float pr = p0.x * r0.x + p0.y * r0.y + p1.x * r0.z + p1.y * r0.w
             + p2.x * r1.x + p2.y * r1.y + p3.x * r1.z + p3.y * r1.w;

    pl += __shfl_xor_sync(0xffffffffu, pl, 1);
    pl += __shfl_xor_sync(0xffffffffu, pl, 2);
    pr += __shfl_xor_sync(0xffffffffu, pr, 1);
    pr += __shfl_xor_sync(0xffffffffu, pr, 2);
    if (sub == 0) {
        el[node * NHEAD + myh] = pl;
        er[node * NHEAD + myh] = pr;
    }
}

// ================= fused single-pass GAT aggregation, bf16 gather =================
// one warp per dst node; lane owns cols [lane*8, lane*8+8); head = lane>>2.
// mode hout!=null: write per-node row. mode hout==null: block-reduce into csum.
__global__ __launch_bounds__(256) void gat_aggr(const int* __restrict__ rows,
                                                const int* __restrict__ csrc,
                                                const float* __restrict__ el,
                                                const float* __restrict__ er,
                                                const __nv_bfloat16* __restrict__ featb,
                                                const float* __restrict__ hres,
                                                const float* __restrict__ bias,
                                                float* __restrict__ hout,
                                                float* __restrict__ csum) {
    __shared__ float ssum[8][FDIM];
    int tid  = threadIdx.x;
    int node = (blockIdx.x * blockDim.x + tid) >> 5;   // grid sized exactly -> always valid
    int lane = tid & 31;
    int w    = tid >> 5;
    int myh  = lane >> 2;

    int e0 = rows[node], e1 = rows[node + 1];
    float er_my = er[node * NHEAD + myh];

    float acc[8] = {};
    float den = 0.f;
    const uint4* fb4 = (const uint4*)featb;            // 8 bf16 per uint4; 32 per row
    for (int e = e0; e < e1; e++) {
        int s = csrc[e];                               // warp-uniform broadcast load
        float v = __ldg(&el[s * NHEAD + myh]) + er_my;
        v = (v > 0.f) ? v : NEG_SLOPE * v;
        float a = __expf(v);
        den += a;
        uint4 q = fb4[(long)s * 32 + lane];            // cols [lane*8, lane*8+8)
        float2 p0 = __bfloat1622float2(*reinterpret_cast<__nv_bfloat162*>(&q.x));
        float2 p1 = __bfloat1622float2(*reinterpret_cast<__nv_bfloat162*>(&q.y));
        float2 p2 = __bfloat1622float2(*reinterpret_cast<__nv_bfloat162*>(&q.z));
        float2 p3 = __bfloat1622float2(*reinterpret_cast<__nv_bfloat162*>(&q.w));
        acc[0] += a * p0.x; acc[1] += a * p0.y;
        acc[2] += a * p1.x; acc[3] += a * p1.y;
        acc[4] += a * p2.x; acc[5] += a * p2.y;
        acc[6] += a * p3.x; acc[7] += a * p3.y;
    }
    float inv = (den == 0.f) ? 1.f : 1.f / den;

    float4 b0 = ((const float4*)bias)[lane * 2];
    float4 b1 = ((const float4*)bias)[lane * 2 + 1];
    float bv[8] = {b0.x, b0.y, b0.z, b0.w, b1.x, b1.y, b1.z, b1.w};
    float rv[8] = {};
    if (hres) {
        float4 r0 = ((const float4*)(hres + (long)node * FDIM))[lane * 2];
        float4 r1 = ((const float4*)(hres + (long)node * FDIM))[lane * 2 + 1];
        rv[0] = r0.x; rv[1] = r0.y; rv[2] = r0.z; rv[3] = r0.w;
        rv[4] = r1.x; rv[5] = r1.y; rv[6] = r1.z; rv[7] = r1.w;
    }
    float o[8];
#pragma unroll
    for (int j = 0; j < 8; j++) {
        float val = acc[j] * inv + rv[j] + bv[j];
        o[j] = (val > 0.f) ? val : expm1f(val);
    }
    if (hout) {
        float* op = hout + (long)node * FDIM + lane * 8;
        *(float4*)op       = make_float4(o[0], o[1], o[2], o[3]);
        *(float4*)(op + 4) = make_float4(o[4], o[5], o[6], o[7]);
    } else {
        // per-warp row in smem (plain stores), tree-sum, 256 global atomics/block
        *(float4*)&ssum[w][lane * 8]     = make_float4(o[0], o[1], o[2], o[3]);
        *(float4*)&ssum[w][lane * 8 + 4] = make_float4(o[4], o[5], o[6], o[7]);
        __syncthreads();
        float s = 0.f;
#pragma unroll
        for (int ww = 0; ww < 8; ww++) s += ssum[ww][tid];
        atomicAdd(&csum[tid], s);
    }
}

// ================= final GEMV (mean commuted through linear) =================
__global__ void zero_csum(float* c) { c[threadIdx.x] = 0.f; }

__global__ void final_k(const float* __restrict__ csum,
                        const float* __restrict__ Wl,
                        const float* __restrict__ bl,
                        float* __restrict__ out) {
    int j = threadIdx.x;
    float s = 0.f;
    for (int c = 0; c < FDIM; c++) s += csum[c] * Wl[c * 128 + j];
    out[j] = s * (1.f / (float)N_NODES) + bl[j];
}

// ================= host =================
extern "C" void kernel_launch(void* const* d_in, const int* in_sizes, int n_in,
                              void* d_out, int out_size) {
    const float* x   = (const float*)d_in[0];
    const int*   src = (const int*)  d_in[1];
    const int*   dst = (const int*)  d_in[2];
    const float* W1  = (const float*)d_in[3];
    const float* al1 = (const float*)d_in[4];
    const float* ar1 = (const float*)d_in[5];
    const float* b1  = (const float*)d_in[6];
    const float* W2  = (const float*)d_in[7];
    const float* al2 = (const float*)d_in[8];
    const float* ar2 = (const float*)d_in[9];
    const float* b2  = (const float*)d_in[10];
    const float* Wl  = (const float*)d_in[11];
    const float* bl  = (const float*)d_in[12];
    float* out = (float*)d_out;

    float *h1, *el, *er, *csum;
    __nv_bfloat16* featb;
    int *cnt, *rows, *cur, *csrc, *bsum, *boff;
    cudaGetSymbolAddress((void**)&featb, g_featb);
    cudaGetSymbolAddress((void**)&h1,    g_h1);
    cudaGetSymbolAddress((void**)&el,    g_el);
    cudaGetSymbolAddress((void**)&er,    g_er);
    cudaGetSymbolAddress((void**)&csum,  g_csum);
    cudaGetSymbolAddress((void**)&cnt,   g_cnt);
    cudaGetSymbolAddress((void**)&rows,  g_rows);
    cudaGetSymbolAddress((void**)&cur,   g_cur);
    cudaGetSymbolAddress((void**)&csrc,  g_csrc);
    cudaGetSymbolAddress((void**)&bsum,  g_bsum);
    cudaGetSymbolAddress((void**)&boff,  g_boff);

    int nodeBlocks     = (N_NODES + 255) / 256;     // 196
    int edgeBlocks     = (N_EDGES + 255) / 256;
    int nodeWarpBlocks = (N_NODES * 32) / 256;      // 6250 exact
    dim3 gemm_grid(FDIM / GN, (N_NODES + GM - 1) / GM);

    // CSR build + layer-1 projection (sgemm stays the 4th launch -> profiled)
    zero_cnt<<<nodeBlocks, 256>>>(cnt);
    hist_k<<<edgeBlocks, 256>>>(dst, cnt);
    scan1_k<<<nodeBlocks, 256>>>(cnt, rows, bsum);
    sgemm_tf32<<<gemm_grid, 256>>>(x, W1, featb, N_NODES, 128);
    scan2_k<<<1, 256>>>(bsum, boff);
    scan3_k<<<nodeBlocks, 256>>>(rows, boff, cur);
    scatter_k<<<edgeBlocks, 256>>>(src, dst, cur, csrc);

    // layer 1 (no residual)
    node_prep<<<nodeWarpBlocks, 256>>>(featb, al1, ar1, el, er);
    gat_aggr<<<nodeWarpBlocks, 256>>>(rows, csrc, el, er, featb, nullptr, b1, h1, nullptr);

    // layer 2 (identity residual) — output block-reduced straight into csum
    sgemm_tf32<<<gemm_grid, 256>>>(h1, W2, featb, N_NODES, 256);
    node_prep<<<nodeWarpBlocks, 256>>>(featb, al2, ar2, el, er);
    zero_csum<<<1, FDIM>>>(csum);
    gat_aggr<<<nodeWarpBlocks, 256>>>(rows, csrc, el, er, featb, h1, b2, nullptr, csum);

    // out = colmean(h2) @ Wl + bl
    final_k<<<1, 128>>>(csum, Wl, bl, out);
}

// round 15
// speedup vs baseline: 1.8434x; 1.1217x over previous
#include <cuda_runtime.h>
#include <cuda_fp16.h>
#include <math.h>

#define N_NODES 50000
#define N_EDGES 800000
#define NHEAD 8
#define HIDD 32
#define FDIM 256
#define NEG_SLOPE 0.2f
#define NSCAN_BLOCKS 196   /* ceil(50000/256) */

// ---------------- scratch ----------------
__device__ __half g_xh   [N_NODES * 128];    // x in fp16
__device__ __half g_w1t  [256 * 128];        // W1^T fp16 [n][k]
__device__ __half g_w2t  [256 * 256];        // W2^T fp16 [n][k]
__device__ __half g_feath[N_NODES * FDIM];   // projected features (fp16)
__device__ __half g_h1h  [N_NODES * FDIM];   // layer-1 output (fp16: GEMM2 A + residual)
__device__ float  g_el   [N_NODES * NHEAD];
__device__ float  g_er   [N_NODES * NHEAD];
__device__ float  g_csum [FDIM];
__device__ int    g_cnt  [N_NODES];
__device__ int    g_rows [N_NODES + 1];
__device__ int    g_cur  [N_NODES];
__device__ int    g_csrc [N_EDGES];
__device__ int    g_bsum [NSCAN_BLOCKS];
__device__ int    g_boff [NSCAN_BLOCKS];

// ================= conversions =================
__global__ __launch_bounds__(256) void conv_x_k(const float* __restrict__ x,
                                                __half* __restrict__ xh) {
    long i = (long)blockIdx.x * blockDim.x + threadIdx.x;      // per 4 elems
    if (i * 4 >= (long)N_NODES * 128) return;
    float4 v = ((const float4*)x)[i];
    ((__half2*)xh)[i * 2]     = __floats2half2_rn(v.x, v.y);
    ((__half2*)xh)[i * 2 + 1] = __floats2half2_rn(v.z, v.w);
}
// W [K,256] fp32 -> Wt [256][K] fp16 (transposed)
__global__ __launch_bounds__(256) void conv_w_k(const float* __restrict__ W,
                                                __half* __restrict__ Wt, int K) {
    int idx = blockIdx.x * 256 + threadIdx.x;                  // k*256+n
    if (idx >= K * 256) return;
    int k = idx >> 8, n = idx & 255;
    Wt[n * K + k] = __float2half(W[idx]);
}

// ================= CSR build =================
__global__ void zero_cnt(int* cnt) {
    int i = blockIdx.x * blockDim.x + threadIdx.x;
    if (i < N_NODES) cnt[i] = 0;
}
__global__ void hist_k(const int* __restrict__ dst, int* __restrict__ cnt) {
    int e = blockIdx.x * blockDim.x + threadIdx.x;
    if (e < N_EDGES) atomicAdd(&cnt[dst[e]], 1);
}
__global__ __launch_bounds__(256) void scan1_k(const int* __restrict__ cnt,
                                               int* __restrict__ rows,
                                               int* __restrict__ bsum) {
    __shared__ int ws[8];
    int t = threadIdx.x, lane = t & 31, w = t >> 5;
    int i = blockIdx.x * 256 + t;
    int v = (i < N_NODES) ? cnt[i] : 0;
    int x = v;
#pragma unroll
    for (int o = 1; o < 32; o <<= 1) {
        int y = __shfl_up_sync(0xffffffffu, x, o);
        if (lane >= o) x += y;
    }
    if (lane == 31) ws[w] = x;
    __syncthreads();
    if (w == 0 && lane < 8) {
        int y = ws[lane];
#pragma unroll
        for (int o = 1; o < 8; o <<= 1) {
            int z = __shfl_up_sync(0x000000ffu, y, o);
            if (lane >= o) y += z;
        }
        ws[lane] = y;
    }
    __syncthreads();
    int excl = x - v + (w ? ws[w - 1] : 0);
    if (i < N_NODES) rows[i] = excl;
    if (t == 255) bsum[blockIdx.x] = excl + v;
}
__global__ __launch_bounds__(256) void scan2_k(const int* __restrict__ bsum,
                                               int* __restrict__ boff) {
    __shared__ int ws[8];
    int t = threadIdx.x, lane = t & 31, w = t >> 5;
    int v = (t < NSCAN_BLOCKS) ? bsum[t] : 0;
    int x = v;
#pragma unroll
    for (int o = 1; o < 32; o <<= 1) {
        int y = __shfl_up_sync(0xffffffffu, x, o);
        if (lane >= o) x += y;
    }
    if (lane == 31) ws[w] = x;
    __syncthreads();
    if (w == 0 && lane < 8) {
        int y = ws[lane];
#pragma unroll
        for (int o = 1; o < 8; o <<= 1) {
            int z = __shfl_up_sync(0x000000ffu, y, o);
            if (lane >= o) y += z;
        }
        ws[lane] = y;
    }
    __syncthreads();
    if (t < NSCAN_BLOCKS) boff[t] = x - v + (w ? ws[w - 1] : 0);
}
__global__ __launch_bounds__(256) void scan3_k(int* __restrict__ rows,
                                               const int* __restrict__ boff,
                                               int* __restrict__ cur) {
    int i = blockIdx.x * 256 + threadIdx.x;
    if (i < N_NODES) {
        int r = rows[i] + boff[blockIdx.x];
        rows[i] = r;
        cur[i]  = r;
    }
    if (i == 0) rows[N_NODES] = N_EDGES;
}
__global__ void scatter_k(const int* __restrict__ src, const int* __restrict__ dst,
                          int* __restrict__ cur, int* __restrict__ csrc) {
    int e = blockIdx.x * blockDim.x + threadIdx.x;
    if (e < N_EDGES) {
        int pos = atomicAdd(&cur[dst[e]], 1);
        csrc[pos] = src[e];
    }
}

// ================= FP16 tensor-core GEMM: C[M,256] = A[M,K] @ Wt^T =================
// A fp16 [M,K] row-major; Wt fp16 [256][K] (so mma's col-major B reads Wt rows).
// block 128x128, 8 warps 2x4, warp 64x32 = 4x4 mma(16x8x16); k-block 16.
__device__ __forceinline__ void mma_f16(float c[4], const unsigned a[4], const unsigned b[2]) {
    asm volatile(
        "mma.sync.aligned.m16n8k16.row.col.f32.f16.f16.f32 "
        "{%0,%1,%2,%3}, {%4,%5,%6,%7}, {%8,%9}, {%0,%1,%2,%3};\n"
        : "+f"(c[0]), "+f"(c[1]), "+f"(c[2]), "+f"(c[3])
        : "r"(a[0]), "r"(a[1]), "r"(a[2]), "r"(a[3]), "r"(b[0]), "r"(b[1]));
}

#define GM 128
#define GN 128
#define GKB 16

__global__ __launch_bounds__(256, 2) void hgemm(const __half* __restrict__ A,
                                                const __half* __restrict__ Wt,
                                                __half* __restrict__ C,
                                                int M, int K) {
    // [row][kpair-word], pad 20 words: r*20 mod 32 distinct over 8 frag rows; 16B-aligned uint4 slots
    __shared__ unsigned As[2][GM][20];
    __shared__ unsigned Bs[2][GN][20];
    int tid  = threadIdx.x;
    int warp = tid >> 5, lane = tid & 31;
    int wm = warp >> 2, wn = warp & 3;
    int rowBase = blockIdx.y * GM;
    int colBase = blockIdx.x * GN;
    int nk = K / GKB;

    int qr = lane >> 2, qc = lane & 3;

    int l_row  = tid >> 1;          // 0..127 (A m-row / B n-row)
    int l_half = (tid & 1) * 4;     // word offset 0 or 4 (k 0..7 / 8..15)

    const uint4 uz = make_uint4(0u, 0u, 0u, 0u);
    uint4 pa, pb;

    {
        int g = rowBase + l_row;
        pa = (g < M) ? *(const uint4*)(A + (long)g * K + l_half * 2) : uz;
        pb = *(const uint4*)(Wt + (long)(colBase + l_row) * K + l_half * 2);
    }
    *(uint4*)&As[0][l_row][l_half] = pa;
    *(uint4*)&Bs[0][l_row][l_half] = pb;
    __syncthreads();

    float cacc[4][4][4] = {};

    for (int kb = 0; kb < nk; kb++) {
        int nb = kb + 1;
        if (nb < nk) {
            int koff = nb * GKB;
            int g = rowBase + l_row;
            pa = (g < M) ? *(const uint4*)(A + (long)g * K + koff + l_half * 2) : uz;
            pb = *(const uint4*)(Wt + (long)(colBase + l_row) * K + koff + l_half * 2);
        }
        int cb = kb & 1;
        {
            unsigned af[4][4], bf[4][2];
#pragma unroll
            for (int mi = 0; mi < 4; mi++) {
                int r = wm * 64 + mi * 16 + qr;
                af[mi][0] = As[cb][r][qc];
                af[mi][1] = As[cb][r + 8][qc];
                af[mi][2] = As[cb][r][qc + 4];
                af[mi][3] = As[cb][r + 8][qc + 4];
            }
#pragma unroll
            for (int ni = 0; ni < 4; ni++) {
                int n = wn * 32 + ni * 8 + qr;
                bf[ni][0] = Bs[cb][n][qc];
                bf[ni][1] = Bs[cb][n][qc + 4];
            }
#pragma unroll
            for (int mi = 0; mi < 4; mi++)
#pragma unroll
                for (int ni = 0; ni < 4; ni++)
                    mma_f16(cacc[mi][ni], af[mi], bf[ni]);
        }
        if (nb < nk) {
            int wb = nb & 1;
            *(uint4*)&As[wb][l_row][l_half] = pa;
            *(uint4*)&Bs[wb][l_row][l_half] = pb;
        }
        __syncthreads();
    }

    // store C fp16
#pragma unroll
    for (int mi = 0; mi < 4; mi++) {
        int r0 = rowBase + wm * 64 + mi * 16 + qr;
        int r1 = r0 + 8;
#pragma unroll
        for (int ni = 0; ni < 4; ni++) {
            int c = colBase + wn * 32 + ni * 8 + 2 * qc;
            if (r0 < M)
                *(__half2*)(C + (long)r0 * FDIM + c) =
                    __floats2half2_rn(cacc[mi][ni][0], cacc[mi][ni][1]);
            if (r1 < M)
                *(__half2*)(C + (long)r1 * FDIM + c) =
                    __floats2half2_rn(cacc[mi][ni][2], cacc[mi][ni][3]);
        }
    }
}

// ================= node prep: el/er from fp16 feat (one uint4/lane) =================
__global__ __launch_bounds__(256) void node_prep(const __half* __restrict__ feath,
                                                 const float* __restrict__ al,
                                                 const float* __restrict__ ar,
                                                 float* __restrict__ el,
                                                 float* __restrict__ er) {
    int node = (blockIdx.x * blockDim.x + threadIdx.x) >> 5;  // grid exact
    int lane = threadIdx.x & 31;
    int myh = lane >> 2, sub = lane & 3;

    uint4 q = ((const uint4*)feath)[(long)node * 32 + lane];
    float2 p0 = __half22float2(*reinterpret_cast<__half2*>(&q.x));
    float2 p1 = __half22float2(*reinterpret_cast<__half2*>(&q.y));
    float2 p2 = __half22float2(*reinterpret_cast<__half2*>(&q.z));
    float2 p3 = __half22float2(*reinterpret_cast<__half2*>(&q.w));

    const float4* al4 = (const float4*)(al + myh * HIDD + sub * 8);
    const float4* ar4 = (const float4*)(ar + myh * HIDD + sub * 8);
    float4 a0 = al4[0], a1 = al4[1];
    float4 r0 = ar4[0], r1 = ar4[1];

    float pl = p0.x * a0.x + p0.y * a0.y + p1.x * a0.z + p1.y * a0.w
             + p2.x * a1.x + p2.y * a1.y + p3.x * a1.z + p3.y * a1.w;
    float pr = p0.x * r0.x + p0.y * r0.y + p1.x * r0.z + p1.y * r0.w
             + p2.x * r1.x + p2.y * r1.y + p3.x * r1.z + p3.y * r1.w;

    pl += __shfl_xor_sync(0xffffffffu, pl, 1);
    pl += __shfl_xor_sync(0xffffffffu, pl, 2);
    pr += __shfl_xor_sync(0xffffffffu, pr, 1);
    pr += __shfl_xor_sync(0xffffffffu, pr, 2);
    if (sub == 0) {
        el[node * NHEAD + myh] = pl;
        er[node * NHEAD + myh] = pr;
    }
}

// ================= fused single-pass GAT aggregation, fp16 gather =================
// one warp per dst node; lane owns cols [lane*8, lane*8+8); head = lane>>2.
// mode hout!=null: write fp16 row. mode hout==null: block-reduce into csum (fp32).
__global__ __launch_bounds__(256) void gat_aggr(const int* __restrict__ rows,
                                                const int* __restrict__ csrc,
                                                const float* __restrict__ el,
                                                const float* __restrict__ er,
                                                const __half* __restrict__ feath,
                                                const __half* __restrict__ hres,
                                                const float* __restrict__ bias,
                                                __half* __restrict__ hout,
                                                float* __restrict__ csum) {
    __shared__ float ssum[8][FDIM];
    int tid  = threadIdx.x;
    int node = (blockIdx.x * blockDim.x + tid) >> 5;   // grid sized exactly -> always valid
    int lane = tid & 31;
    int w    = tid >> 5;
    int myh  = lane >> 2;

    int e0 = rows[node], e1 = rows[node + 1];
    float er_my = er[node * NHEAD + myh];

    float acc[8] = {};
    float den = 0.f;
    const uint4* fh4 = (const uint4*)feath;            // 8 fp16 per uint4; 32 per row
    for (int e = e0; e < e1; e++) {
        int s = csrc[e];                               // warp-uniform broadcast load
        float v = __ldg(&el[s * NHEAD + myh]) + er_my;
        v = (v > 0.f) ? v : NEG_SLOPE * v;
        float a = __expf(v);
        den += a;
        uint4 q = fh4[(long)s * 32 + lane];
        float2 p0 = __half22float2(*reinterpret_cast<__half2*>(&q.x));
        float2 p1 = __half22float2(*reinterpret_cast<__half2*>(&q.y));
        float2 p2 = __half22float2(*reinterpret_cast<__half2*>(&q.z));
        float2 p3 = __half22float2(*reinterpret_cast<__half2*>(&q.w));
        acc[0] += a * p0.x; acc[1] += a * p0.y;
        acc[2] += a * p1.x; acc[3] += a * p1.y;
        acc[4] += a * p2.x; acc[5] += a * p2.y;
        acc[6] += a * p3.x; acc[7] += a * p3.y;
    }
    float inv = (den == 0.f) ? 1.f : 1.f / den;

    float4 b0 = ((const float4*)bias)[lane * 2];
    float4 b1 = ((const float4*)bias)[lane * 2 + 1];
    float bv[8] = {b0.x, b0.y, b0.z, b0.w, b1.x, b1.y, b1.z, b1.w};
    float rv[8] = {};
    if (hres) {
        uint4 q = ((const uint4*)hres)[(long)node * 32 + lane];
        float2 r0 = __half22float2(*reinterpret_cast<__half2*>(&q.x));
        float2 r1 = __half22float2(*reinterpret_cast<__half2*>(&q.y));
        float2 r2 = __half22float2(*reinterpret_cast<__half2*>(&q.z));
        float2 r3 = __half22float2(*reinterpret_cast<__half2*>(&q.w));
        rv[0] = r0.x; rv[1] = r0.y; rv[2] = r1.x; rv[3] = r1.y;
        rv[4] = r2.x; rv[5] = r2.y; rv[6] = r3.x; rv[7] = r3.y;
    }
    float o[8];
#pragma unroll
    for (int j = 0; j < 8; j++) {
        float val = acc[j] * inv + rv[j] + bv[j];
        o[j] = (val > 0.f) ? val : expm1f(val);
    }
    if (hout) {
        uint4 q;
        *reinterpret_cast<__half2*>(&q.x) = __floats2half2_rn(o[0], o[1]);
        *reinterpret_cast<__half2*>(&q.y) = __floats2half2_rn(o[2], o[3]);
        *reinterpret_cast<__half2*>(&q.z) = __floats2half2_rn(o[4], o[5]);
        *reinterpret_cast<__half2*>(&q.w) = __floats2half2_rn(o[6], o[7]);
        ((uint4*)hout)[(long)node * 32 + lane] = q;
    } else {
        *(float4*)&ssum[w][lane * 8]     = make_float4(o[0], o[1], o[2], o[3]);
        *(float4*)&ssum[w][lane * 8 + 4] = make_float4(o[4], o[5], o[6], o[7]);
        __syncthreads();
        float s = 0.f;
#pragma unroll
        for (int ww = 0; ww < 8; ww++) s += ssum[ww][tid];
        atomicAdd(&csum[tid], s);
    }
}

// ================= final GEMV (mean commuted through linear) =================
__global__ void zero_csum(float* c) { c[threadIdx.x] = 0.f; }

__global__ void final_k(const float* __restrict__ csum,
                        const float* __restrict__ Wl,
                        const float* __restrict__ bl,
                        float* __restrict__ out) {
    int j = threadIdx.x;
    float s = 0.f;
    for (int c = 0; c < FDIM; c++) s += csum[c] * Wl[c * 128 + j];
    out[j] = s * (1.f / (float)N_NODES) + bl[j];
}

// ================= host =================
extern "C" void kernel_launch(void* const* d_in, const int* in_sizes, int n_in,
                              void* d_out, int out_size) {
    const float* x   = (const float*)d_in[0];
    const int*   src = (const int*)  d_in[1];
    const int*   dst = (const int*)  d_in[2];
    const float* W1  = (const float*)d_in[3];
    const float* al1 = (const float*)d_in[4];
    const float* ar1 = (const float*)d_in[5];
    const float* b1  = (const float*)d_in[6];
    const float* W2  = (const float*)d_in[7];
    const float* al2 = (const float*)d_in[8];
    const float* ar2 = (const float*)d_in[9];
    const float* b2  = (const float*)d_in[10];
    const float* Wl  = (const float*)d_in[11];
    const float* bl  = (const float*)d_in[12];
    float* out = (float*)d_out;

    float *el, *er, *csum;
    __half *xh, *w1t, *w2t, *feath, *h1h;
    int *cnt, *rows, *cur, *csrc, *bsum, *boff;
    cudaGetSymbolAddress((void**)&xh,    g_xh);
    cudaGetSymbolAddress((void**)&w1t,   g_w1t);
    cudaGetSymbolAddress((void**)&w2t,   g_w2t);
    cudaGetSymbolAddress((void**)&feath, g_feath);
    cudaGetSymbolAddress((void**)&h1h,   g_h1h);
    cudaGetSymbolAddress((void**)&el,    g_el);
    cudaGetSymbolAddress((void**)&er,    g_er);
    cudaGetSymbolAddress((void**)&csum,  g_csum);
    cudaGetSymbolAddress((void**)&cnt,   g_cnt);
    cudaGetSymbolAddress((void**)&rows,  g_rows);
    cudaGetSymbolAddress((void**)&cur,   g_cur);
    cudaGetSymbolAddress((void**)&csrc,  g_csrc);
    cudaGetSymbolAddress((void**)&bsum,  g_bsum);
    cudaGetSymbolAddress((void**)&boff,  g_boff);

    int nodeBlocks     = (N_NODES + 255) / 256;     // 196
    int edgeBlocks     = (N_EDGES + 255) / 256;
    int nodeWarpBlocks = (N_NODES * 32) / 256;      // 6250 exact
    int convXBlocks    = (int)(((long)N_NODES * 128 / 4 + 255) / 256);
    dim3 gemm_grid(FDIM / GN, (N_NODES + GM - 1) / GM);

    // conversions + CSR build (independent work interleaved)
    conv_x_k<<<convXBlocks, 256>>>(x, xh);
    conv_w_k<<<(128 * 256 + 255) / 256, 256>>>(W1, w1t, 128);
    conv_w_k<<<(256 * 256 + 255) / 256, 256>>>(W2, w2t, 256);
    zero_cnt<<<nodeBlocks, 256>>>(cnt);
    hist_k<<<edgeBlocks, 256>>>(dst, cnt);
    scan1_k<<<nodeBlocks, 256>>>(cnt, rows, bsum);

    // layer 1 projection
    hgemm<<<gemm_grid, 256>>>(xh, w1t, feath, N_NODES, 128);
    scan2_k<<<1, 256>>>(bsum, boff);
    scan3_k<<<nodeBlocks, 256>>>(rows, boff, cur);
    scatter_k<<<edgeBlocks, 256>>>(src, dst, cur, csrc);

    // layer 1 aggregation (no residual) -> h1 fp16
    node_prep<<<nodeWarpBlocks, 256>>>(feath, al1, ar1, el, er);
    gat_aggr<<<nodeWarpBlocks, 256>>>(rows, csrc, el, er, feath, nullptr, b1, h1h, nullptr);

    // layer 2 (identity residual) — output block-reduced straight into csum
    hgemm<<<gemm_grid, 256>>>(h1h, w2t, feath, N_NODES, 256);
    node_prep<<<nodeWarpBlocks, 256>>>(feath, al2, ar2, el, er);
    zero_csum<<<1, FDIM>>>(csum);
    gat_aggr<<<nodeWarpBlocks, 256>>>(rows, csrc, el, er, feath, h1h, b2, nullptr, csum);

    // out = colmean(h2) @ Wl + bl
    final_k<<<1, 128>>>(csum, Wl, bl, out);
}